// round 4
// baseline (speedup 1.0000x reference)
#include <cuda_runtime.h>
#include <cuda_bf16.h>
#include <math.h>

#define B_   2048
#define A_   256
#define ED_  200
#define RD_  200
#define HD_  400
#define XD_  800
#define AD_  400
#define HUGE_ 1e9f

__device__ float g_h1[B_ * AD_];
__device__ float g_X2[B_ * AD_];

// ---------------------------------------------------------------------------
// SGEMM: 128x64 tile, BK=16, 256 threads, 8x4 per thread, double-buffered.
// STAGE 0: A = [E(e)|H|Q(q)] gathered on the fly (K=800), C=g_h1, ReLU
// STAGE 1: A = g_h1 (K=400), C=g_X2
// ---------------------------------------------------------------------------
template<int STAGE>
__global__ void __launch_bounds__(256)
sgemm_kernel(const float* __restrict__ Bm,
             const float* __restrict__ bias,
             const int* __restrict__ e,
             const int* __restrict__ q,
             const float* __restrict__ H,
             const float* __restrict__ ent_emb,
             const float* __restrict__ rel_emb) {
    const int K = (STAGE == 0) ? XD_ : AD_;
    const int N = AD_;
    float* C = (STAGE == 0) ? g_h1 : g_X2;

    __shared__ float As[2][16][128];
    __shared__ float Bs[2][16][64];

    const int tid = threadIdx.x;
    const int bm = blockIdx.y * 128;
    const int bn = blockIdx.x * 64;

    // A loader: each thread loads 8 floats (2 float4) of one row
    const int ar = tid >> 1;              // 0..127 row in tile
    const int ac = (tid & 1) << 3;        // 0 or 8: col base in k-tile
    // B loader: one float4
    const int br = tid >> 4;              // 0..15
    const int bc = (tid & 15) << 2;       // 0..60

    // Row source pointers (stage 0 gathers from three sources)
    const int row = bm + ar;
    const float* eptr;
    const float* hptr;
    const float* qptr;
    const float* aptr;
    if (STAGE == 0) {
        eptr = ent_emb + (long)e[row] * ED_;
        hptr = H + (long)row * HD_;
        qptr = rel_emb + (long)q[row] * RD_;
    } else {
        aptr = g_h1 + (long)row * AD_;
    }

    auto loadA4 = [&](int c) -> float4 {
        if (STAGE == 0) {
            // 8-float chunks never straddle 200/600 boundaries (all mult of 8)
            if (c < ED_)            return *reinterpret_cast<const float4*>(eptr + c);
            else if (c < ED_ + HD_) return *reinterpret_cast<const float4*>(hptr + (c - ED_));
            else                    return *reinterpret_cast<const float4*>(qptr + (c - ED_ - HD_));
        } else {
            return *reinterpret_cast<const float4*>(aptr + c);
        }
    };
    auto loadB = [&](int t) -> float4 {
        int n = bn + bc;
        int kk = t * 16 + br;
        if (n + 3 < N) {
            return *reinterpret_cast<const float4*>(&Bm[(long)kk * N + n]);
        } else {
            float4 v;
            v.x = (n + 0 < N) ? Bm[(long)kk * N + n + 0] : 0.f;
            v.y = (n + 1 < N) ? Bm[(long)kk * N + n + 1] : 0.f;
            v.z = (n + 2 < N) ? Bm[(long)kk * N + n + 2] : 0.f;
            v.w = 0.f;
            return v;
        }
    };

    // compute mapping: 8 rows x 4 cols
    const int ty = tid >> 4;    // 0..15 -> rows ty*8..+7
    const int tx = tid & 15;    // 0..15 -> cols tx*4..+3

    float acc[8][4] = {};
    const int nt = K / 16;

    // preload tile 0
    {
        float4 a0 = loadA4(ac);
        float4 a1 = loadA4(ac + 4);
        float4 vb = loadB(0);
        As[0][ac + 0][ar] = a0.x; As[0][ac + 1][ar] = a0.y;
        As[0][ac + 2][ar] = a0.z; As[0][ac + 3][ar] = a0.w;
        As[0][ac + 4][ar] = a1.x; As[0][ac + 5][ar] = a1.y;
        As[0][ac + 6][ar] = a1.z; As[0][ac + 7][ar] = a1.w;
        Bs[0][br][bc + 0] = vb.x; Bs[0][br][bc + 1] = vb.y;
        Bs[0][br][bc + 2] = vb.z; Bs[0][br][bc + 3] = vb.w;
    }
    __syncthreads();

    for (int t = 0; t < nt; t++) {
        const int cur = t & 1;
        float4 pa0, pa1, pb;
        const bool more = (t + 1 < nt);
        if (more) {
            int c = (t + 1) * 16 + ac;
            pa0 = loadA4(c);
            pa1 = loadA4(c + 4);
            pb  = loadB(t + 1);
        }

        #pragma unroll
        for (int k = 0; k < 16; k++) {
            float4 a0 = *reinterpret_cast<const float4*>(&As[cur][k][ty << 3]);
            float4 a1 = *reinterpret_cast<const float4*>(&As[cur][k][(ty << 3) + 4]);
            float4 bv = *reinterpret_cast<const float4*>(&Bs[cur][k][tx << 2]);
            float am[8] = {a0.x, a0.y, a0.z, a0.w, a1.x, a1.y, a1.z, a1.w};
            float bnv[4] = {bv.x, bv.y, bv.z, bv.w};
            #pragma unroll
            for (int i = 0; i < 8; i++)
                #pragma unroll
                for (int j = 0; j < 4; j++)
                    acc[i][j] += am[i] * bnv[j];
        }

        if (more) {
            const int nxt = cur ^ 1;
            As[nxt][ac + 0][ar] = pa0.x; As[nxt][ac + 1][ar] = pa0.y;
            As[nxt][ac + 2][ar] = pa0.z; As[nxt][ac + 3][ar] = pa0.w;
            As[nxt][ac + 4][ar] = pa1.x; As[nxt][ac + 5][ar] = pa1.y;
            As[nxt][ac + 6][ar] = pa1.z; As[nxt][ac + 7][ar] = pa1.w;
            Bs[nxt][br][bc + 0] = pb.x;  Bs[nxt][br][bc + 1] = pb.y;
            Bs[nxt][br][bc + 2] = pb.z;  Bs[nxt][br][bc + 3] = pb.w;
        }
        __syncthreads();
    }

    #pragma unroll
    for (int i = 0; i < 8; i++) {
        int m = bm + (ty << 3) + i;
        #pragma unroll
        for (int j = 0; j < 4; j++) {
            int n = bn + (tx << 2) + j;
            if (n < N) {
                float c = acc[i][j] + bias[n];
                if (STAGE == 0) c = fmaxf(c, 0.f);
                C[(long)m * N + n] = c;
            }
        }
    }
}

__device__ __forceinline__ float dot4(float4 a, float4 b) {
    return a.x * b.x + a.y * b.y + a.z * b.z + a.w * b.w;
}

// ---------------------------------------------------------------------------
// Score: one block per batch row, 8 warps. 8 lanes per action -> 4 actions
// in flight per warp iteration; group-local 3-shuffle reduction.
// ---------------------------------------------------------------------------
__global__ void __launch_bounds__(256, 6)
score_kernel(const int* __restrict__ r_space,
             const int* __restrict__ e_space,
             const int* __restrict__ action_mask,
             const float* __restrict__ rel_emb,
             const float* __restrict__ ent_emb,
             float* __restrict__ out_dist,
             float* __restrict__ out_ent) {
    const int b = blockIdx.x;
    const int tid = threadIdx.x;
    const int lane = tid & 31;
    const int warp = tid >> 5;
    const int grp = lane >> 3;    // 0..3: action slot within iteration
    const int gl = lane & 7;      // 0..7: lane within 8-lane group
    const unsigned FULL = 0xffffffffu;

    __shared__ float4 x2a[100];   // [0..49] rel half of X2, [50..99] ent half
    __shared__ float sc[A_];
    __shared__ float red[8];

    if (tid < 100)
        x2a[tid] = reinterpret_cast<const float4*>(g_X2 + (long)b * AD_)[tid];
    __syncthreads();

    const long base = (long)b * A_;
    const int aidx = warp * 32 + lane;
    const int my_r = r_space[base + aidx];
    const int my_e = e_space[base + aidx];
    const int my_m = action_mask[base + aidx];

    #pragma unroll
    for (int i = 0; i < 8; i++) {
        const int sl = i * 4 + grp;   // which of this warp's 32 actions
        int rr = __shfl_sync(FULL, my_r, sl);
        int ee = __shfl_sync(FULL, my_e, sl);
        int mm = __shfl_sync(FULL, my_m, sl);

        const float4* rp = reinterpret_cast<const float4*>(rel_emb + (long)rr * RD_);
        const float4* ep = reinterpret_cast<const float4*>(ent_emb + (long)ee * ED_);

        float s = 0.f;
        #pragma unroll
        for (int c = 0; c < 6; c++) {
            float4 rv = rp[c * 8 + gl];
            float4 ev = ep[c * 8 + gl];
            s += dot4(rv, x2a[c * 8 + gl]) + dot4(ev, x2a[50 + c * 8 + gl]);
        }
        if (gl < 2) {   // tail: floats 192..199 of each half
            float4 rv = rp[48 + gl];
            float4 ev = ep[48 + gl];
            s += dot4(rv, x2a[48 + gl]) + dot4(ev, x2a[98 + gl]);
        }

        // 8-lane group reduction (stays within group under xor 1,2,4)
        s += __shfl_xor_sync(FULL, s, 1);
        s += __shfl_xor_sync(FULL, s, 2);
        s += __shfl_xor_sync(FULL, s, 4);

        if (gl == 0) sc[warp * 32 + sl] = s - (1.0f - (float)mm) * HUGE_;
    }
    __syncthreads();

    float v = sc[tid];

    // block max
    float mx = v;
    #pragma unroll
    for (int o = 16; o; o >>= 1) mx = fmaxf(mx, __shfl_xor_sync(FULL, mx, o));
    if (lane == 0) red[warp] = mx;
    __syncthreads();
    if (warp == 0) {
        float mm2 = red[lane & 7];
        #pragma unroll
        for (int o = 4; o; o >>= 1) mm2 = fmaxf(mm2, __shfl_xor_sync(FULL, mm2, o));
        if (lane == 0) red[0] = mm2;
    }
    __syncthreads();
    mx = red[0];
    __syncthreads();

    // exp + sum
    float ev = expf(v - mx);
    float sm = ev;
    #pragma unroll
    for (int o = 16; o; o >>= 1) sm += __shfl_xor_sync(FULL, sm, o);
    if (lane == 0) red[warp] = sm;
    __syncthreads();
    if (warp == 0) {
        float ss = red[lane & 7];
        #pragma unroll
        for (int o = 4; o; o >>= 1) ss += __shfl_xor_sync(FULL, ss, o);
        if (lane == 0) red[0] = ss;
    }
    __syncthreads();
    float total = red[0];
    __syncthreads();

    float p = ev / total;
    out_dist[base + tid] = p;

    // entropy
    float t = p * logf(fmaxf(p, 1e-20f));
    float es = t;
    #pragma unroll
    for (int o = 16; o; o >>= 1) es += __shfl_xor_sync(FULL, es, o);
    if (lane == 0) red[warp] = es;
    __syncthreads();
    if (warp == 0) {
        float ss = red[lane & 7];
        #pragma unroll
        for (int o = 4; o; o >>= 1) ss += __shfl_xor_sync(FULL, ss, o);
        if (lane == 0) out_ent[b] = -ss;
    }
}

extern "C" void kernel_launch(void* const* d_in, const int* in_sizes, int n_in,
                              void* d_out, int out_size) {
    const int*   e        = (const int*)  d_in[0];
    const int*   q        = (const int*)  d_in[1];
    const int*   r_space  = (const int*)  d_in[2];
    const int*   e_space  = (const int*)  d_in[3];
    const int*   mask     = (const int*)  d_in[4];
    const float* H        = (const float*)d_in[5];
    const float* ent_emb  = (const float*)d_in[6];
    const float* rel_emb  = (const float*)d_in[7];
    const float* W1       = (const float*)d_in[8];
    const float* b1       = (const float*)d_in[9];
    const float* W2       = (const float*)d_in[10];
    const float* b2       = (const float*)d_in[11];

    float* out_dist = (float*)d_out;
    float* out_ent  = (float*)d_out + (long)B_ * A_;

    dim3 grid((AD_ + 63) / 64, B_ / 128);   // 7 x 16
    // GEMM1 gathers [E|H|Q] on the fly -> no build_X pass
    sgemm_kernel<0><<<grid, 256>>>(W1, b1, e, q, H, ent_emb, rel_emb);
    sgemm_kernel<1><<<grid, 256>>>(W2, b2, e, q, H, ent_emb, rel_emb);

    score_kernel<<<B_, 256>>>(r_space, e_space, mask, rel_emb, ent_emb,
                              out_dist, out_ent);
}

// round 5
// speedup vs baseline: 1.8149x; 1.8149x over previous
#include <cuda_runtime.h>
#include <cuda_bf16.h>
#include <math.h>

#define B_   2048
#define A_   256
#define ED_  200
#define RD_  200
#define HD_  400
#define XD_  800
#define AD_  400
#define NR_  500
#define HUGE_ 1e9f

__device__ float g_h1[B_ * AD_];
__device__ float g_X2[B_ * AD_];
__device__ float g_P [B_ * NR_];

// ---------------------------------------------------------------------------
// SGEMM 64x64 tile, BK=16, 256 threads, 4x4/thread, double-buffered.
// MODE 0: C=g_h1 = relu([E|H|Q] @ W1 + b1)   K=800 N=400 (A gathered on the fly)
// MODE 1: C=g_X2 = g_h1 @ W2 + b2            K=400 N=400
// MODE 2: C=g_P  = g_X2[:, :200] @ rel_emb^T K=200 N=500 (B transposed, no bias)
// ---------------------------------------------------------------------------
template<int MODE>
__global__ void __launch_bounds__(256)
sgemm_kernel(const float* __restrict__ Bm,
             const float* __restrict__ bias,
             const int* __restrict__ e,
             const int* __restrict__ q,
             const float* __restrict__ H,
             const float* __restrict__ ent_emb,
             const float* __restrict__ rel_emb) {
    const int K = (MODE == 0) ? XD_ : (MODE == 1) ? AD_ : 200;
    const int N = (MODE == 2) ? NR_ : AD_;
    float* C = (MODE == 0) ? g_h1 : (MODE == 1) ? g_X2 : g_P;

    __shared__ float As[2][16][64];
    __shared__ float Bs[2][16][64];

    const int tid = threadIdx.x;
    const int bm = blockIdx.y * 64;
    const int bn = blockIdx.x * 64;

    // A loader: 64x16 tile, 1 float4/thread along k
    const int ar = tid >> 2;
    const int ac = (tid & 3) << 2;
    // B loader (MODE 0/1): 16x64, 1 float4/thread along n
    const int br = tid >> 4;
    const int bc = (tid & 15) << 2;
    // B loader (MODE 2): from rel_emb [N,K]: thread -> (n_local, 4 k's)
    const int nl = tid >> 2;            // 0..63
    const int kc = (tid & 3) << 2;      // 0,4,8,12

    const int row = bm + ar;
    const float* eptr = nullptr;
    const float* hptr = nullptr;
    const float* qptr = nullptr;
    const float* aptr = nullptr;
    if (MODE == 0) {
        eptr = ent_emb + (long)e[row] * ED_;
        hptr = H + (long)row * HD_;
        qptr = rel_emb + (long)q[row] * RD_;
    } else if (MODE == 1) {
        aptr = g_h1 + (long)row * AD_;
    } else {
        aptr = g_X2 + (long)row * AD_;   // only cols < 200 used
    }

    auto loadA4 = [&](int c) -> float4 {
        if (MODE == 0) {
            if (c < ED_)            return *reinterpret_cast<const float4*>(eptr + c);
            else if (c < ED_ + HD_) return *reinterpret_cast<const float4*>(hptr + (c - ED_));
            else                    return *reinterpret_cast<const float4*>(qptr + (c - ED_ - HD_));
        } else if (MODE == 1) {
            return *reinterpret_cast<const float4*>(aptr + c);
        } else {
            if (c < 200) return *reinterpret_cast<const float4*>(aptr + c);
            return make_float4(0.f, 0.f, 0.f, 0.f);
        }
    };

    const int nt = (K + 15) / 16;

    auto stageA = [&](int buf, float4 v) {
        As[buf][ac + 0][ar] = v.x; As[buf][ac + 1][ar] = v.y;
        As[buf][ac + 2][ar] = v.z; As[buf][ac + 3][ar] = v.w;
    };

    // B load+stage per tile
    auto loadB = [&](int t) -> float4 {
        if (MODE != 2) {
            int n = bn + bc;
            int kk = t * 16 + br;
            if (n < N) return *reinterpret_cast<const float4*>(&Bm[(long)kk * N + n]);
            return make_float4(0.f, 0.f, 0.f, 0.f);
        } else {
            int n = bn + nl;
            int k = t * 16 + kc;
            if (n < NR_ && k < 200)
                return *reinterpret_cast<const float4*>(rel_emb + (long)n * RD_ + k);
            return make_float4(0.f, 0.f, 0.f, 0.f);
        }
    };
    auto stageB = [&](int buf, float4 v) {
        if (MODE != 2) {
            Bs[buf][br][bc + 0] = v.x; Bs[buf][br][bc + 1] = v.y;
            Bs[buf][br][bc + 2] = v.z; Bs[buf][br][bc + 3] = v.w;
        } else {
            Bs[buf][kc + 0][nl] = v.x; Bs[buf][kc + 1][nl] = v.y;
            Bs[buf][kc + 2][nl] = v.z; Bs[buf][kc + 3][nl] = v.w;
        }
    };

    const int tx = tid & 15;
    const int ty = tid >> 4;
    float acc[4][4] = {};

    stageA(0, loadA4(ac));
    stageB(0, loadB(0));
    __syncthreads();

    for (int t = 0; t < nt; t++) {
        const int cur = t & 1;
        float4 pa, pb;
        const bool more = (t + 1 < nt);
        if (more) {
            pa = loadA4((t + 1) * 16 + ac);
            pb = loadB(t + 1);
        }

        #pragma unroll
        for (int k = 0; k < 16; k++) {
            float4 av = *reinterpret_cast<const float4*>(&As[cur][k][ty << 2]);
            float4 bv = *reinterpret_cast<const float4*>(&Bs[cur][k][tx << 2]);
            float am[4] = {av.x, av.y, av.z, av.w};
            float bnv[4] = {bv.x, bv.y, bv.z, bv.w};
            #pragma unroll
            for (int i = 0; i < 4; i++)
                #pragma unroll
                for (int j = 0; j < 4; j++)
                    acc[i][j] += am[i] * bnv[j];
        }

        if (more) {
            const int nxt = cur ^ 1;
            stageA(nxt, pa);
            stageB(nxt, pb);
        }
        __syncthreads();
    }

    #pragma unroll
    for (int i = 0; i < 4; i++) {
        int m = bm + (ty << 2) + i;
        #pragma unroll
        for (int j = 0; j < 4; j++) {
            int n = bn + (tx << 2) + j;
            if (n < N) {
                float c = acc[i][j];
                if (MODE != 2) c += bias[n];
                if (MODE == 0) c = fmaxf(c, 0.f);
                C[(long)m * N + n] = c;
            }
        }
    }
}

__device__ __forceinline__ float dot4(float4 a, float4 b) {
    return a.x * b.x + a.y * b.y + a.z * b.z + a.w * b.w;
}

// ---------------------------------------------------------------------------
// Score: one block/batch row, 8 warps. score = P[b, r] + dot(ent_emb[e], X2_ent)
// Masked actions skipped entirely (exact: their softmax prob is 0.0f).
// 8 lanes per action, 4 unmasked actions in flight per iteration.
// ---------------------------------------------------------------------------
__global__ void __launch_bounds__(256, 6)
score_kernel(const int* __restrict__ r_space,
             const int* __restrict__ e_space,
             const int* __restrict__ action_mask,
             const float* __restrict__ ent_emb,
             float* __restrict__ out_dist,
             float* __restrict__ out_ent) {
    const int b = blockIdx.x;
    const int tid = threadIdx.x;
    const int lane = tid & 31;
    const int warp = tid >> 5;
    const int grp = lane >> 3;
    const int gl = lane & 7;
    const unsigned FULL = 0xffffffffu;

    __shared__ float4 x2e[50];            // X2 ent half (cols 200..399)
    __shared__ float sc[A_];
    __shared__ float red[8];
    __shared__ unsigned char alist[8][32];

    if (tid < 50)
        x2e[tid] = reinterpret_cast<const float4*>(g_X2 + (long)b * AD_ + 200)[tid];
    sc[tid] = -1e30f;
    __syncthreads();

    const long base = (long)b * A_;
    const int aidx = warp * 32 + lane;
    const int my_r = r_space[base + aidx];
    const int my_e = e_space[base + aidx];
    const int my_m = action_mask[base + aidx];

    // compact unmasked action lanes
    unsigned mbits = __ballot_sync(FULL, my_m != 0);
    const int cnt = __popc(mbits);
    if (my_m) alist[warp][__popc(mbits & ((1u << lane) - 1u))] = (unsigned char)lane;
    __syncwarp();

    const float* Prow = g_P + (long)b * NR_;

    for (int i0 = 0; i0 < cnt; i0 += 4) {      // cnt warp-uniform
        int i = i0 + grp;
        bool act = (i < cnt);
        int sl = act ? (int)alist[warp][i] : 0;
        int rr = __shfl_sync(FULL, my_r, sl);
        int ee = __shfl_sync(FULL, my_e, sl);

        const float4* ep = reinterpret_cast<const float4*>(ent_emb + (long)ee * ED_);

        float s = 0.f;
        #pragma unroll
        for (int c = 0; c < 6; c++) {
            float4 ev = ep[c * 8 + gl];
            s += dot4(ev, x2e[c * 8 + gl]);
        }
        if (gl < 2) {
            float4 ev = ep[48 + gl];
            s += dot4(ev, x2e[48 + gl]);
        }

        s += __shfl_xor_sync(FULL, s, 1);
        s += __shfl_xor_sync(FULL, s, 2);
        s += __shfl_xor_sync(FULL, s, 4);

        if (act && gl == 0) sc[warp * 32 + sl] = s + Prow[rr];
    }
    __syncthreads();

    float v = sc[tid];

    // block max
    float mx = v;
    #pragma unroll
    for (int o = 16; o; o >>= 1) mx = fmaxf(mx, __shfl_xor_sync(FULL, mx, o));
    if (lane == 0) red[warp] = mx;
    __syncthreads();
    if (warp == 0) {
        float mm = red[lane & 7];
        #pragma unroll
        for (int o = 4; o; o >>= 1) mm = fmaxf(mm, __shfl_xor_sync(FULL, mm, o));
        if (lane == 0) red[0] = mm;
    }
    __syncthreads();
    mx = red[0];
    __syncthreads();

    // exp + sum  (masked: v=-1e30 -> ev==0 exactly)
    float ev = expf(v - mx);
    float sm = ev;
    #pragma unroll
    for (int o = 16; o; o >>= 1) sm += __shfl_xor_sync(FULL, sm, o);
    if (lane == 0) red[warp] = sm;
    __syncthreads();
    if (warp == 0) {
        float ss = red[lane & 7];
        #pragma unroll
        for (int o = 4; o; o >>= 1) ss += __shfl_xor_sync(FULL, ss, o);
        if (lane == 0) red[0] = ss;
    }
    __syncthreads();
    float total = red[0];
    __syncthreads();

    float p = ev / total;
    out_dist[base + tid] = p;

    float t = p * logf(fmaxf(p, 1e-20f));   // p==0 -> 0 contribution
    float es = t;
    #pragma unroll
    for (int o = 16; o; o >>= 1) es += __shfl_xor_sync(FULL, es, o);
    if (lane == 0) red[warp] = es;
    __syncthreads();
    if (warp == 0) {
        float ss = red[lane & 7];
        #pragma unroll
        for (int o = 4; o; o >>= 1) ss += __shfl_xor_sync(FULL, ss, o);
        if (lane == 0) out_ent[b] = -ss;
    }
}

extern "C" void kernel_launch(void* const* d_in, const int* in_sizes, int n_in,
                              void* d_out, int out_size) {
    const int*   e        = (const int*)  d_in[0];
    const int*   q        = (const int*)  d_in[1];
    const int*   r_space  = (const int*)  d_in[2];
    const int*   e_space  = (const int*)  d_in[3];
    const int*   mask     = (const int*)  d_in[4];
    const float* H        = (const float*)d_in[5];
    const float* ent_emb  = (const float*)d_in[6];
    const float* rel_emb  = (const float*)d_in[7];
    const float* W1       = (const float*)d_in[8];
    const float* b1       = (const float*)d_in[9];
    const float* W2       = (const float*)d_in[10];
    const float* b2       = (const float*)d_in[11];

    float* out_dist = (float*)d_out;
    float* out_ent  = (float*)d_out + (long)B_ * A_;

    dim3 g01((AD_ + 63) / 64, B_ / 64);   // 7 x 32 = 224
    dim3 gP ((NR_ + 63) / 64, B_ / 64);   // 8 x 32 = 256

    sgemm_kernel<0><<<g01, 256>>>(W1, b1, e, q, H, ent_emb, rel_emb);
    sgemm_kernel<1><<<g01, 256>>>(W2, b2, e, q, H, ent_emb, rel_emb);
    sgemm_kernel<2><<<gP, 256>>>(nullptr, nullptr, e, q, H, ent_emb, rel_emb);

    score_kernel<<<B_, 256>>>(r_space, e_space, mask, ent_emb,
                              out_dist, out_ent);
}

// round 7
// speedup vs baseline: 2.4616x; 1.3564x over previous
#include <cuda_runtime.h>
#include <cuda_bf16.h>
#include <math.h>
#include <stdint.h>

#define B_   2048
#define A_   256
#define ED_  200
#define RD_  200
#define HD_  400
#define XD_  800
#define AD_  400
#define NR_  500
#define HUGE_ 1e9f

// ---------------- device scratch ----------------
__device__ __nv_bfloat16 g_Ah [B_ * XD_];
__device__ __nv_bfloat16 g_Al [B_ * XD_];
__device__ __nv_bfloat16 g_h1h[B_ * AD_];
__device__ __nv_bfloat16 g_h1l[B_ * AD_];
__device__ float         g_X2 [B_ * AD_];
__device__ __nv_bfloat16 g_X2h[B_ * 200];
__device__ __nv_bfloat16 g_X2l[B_ * 200];
__device__ __nv_bfloat16 g_W1Th[AD_ * XD_];   // [400,800]
__device__ __nv_bfloat16 g_W1Tl[AD_ * XD_];
__device__ __nv_bfloat16 g_W2Th[AD_ * AD_];   // [400,400]
__device__ __nv_bfloat16 g_W2Tl[AD_ * AD_];
__device__ __nv_bfloat16 g_Rh [NR_ * RD_];    // [500,200]
__device__ __nv_bfloat16 g_Rl [NR_ * RD_];
__device__ float         g_P  [B_ * NR_];

// ---------------- helpers ----------------
__device__ __forceinline__ uint32_t smem_u32(const void* p) {
    uint32_t a;
    asm("{ .reg .u64 t; cvta.to.shared.u64 t, %1; cvt.u32.u64 %0, t; }" : "=r"(a) : "l"(p));
    return a;
}
__device__ __forceinline__ void ldsm4(uint32_t* r, uint32_t addr) {
    asm volatile("ldmatrix.sync.aligned.m8n8.x4.shared.b16 {%0,%1,%2,%3}, [%4];"
                 : "=r"(r[0]), "=r"(r[1]), "=r"(r[2]), "=r"(r[3]) : "r"(addr));
}
__device__ __forceinline__ void mma16816(float* c, const uint32_t* a,
                                         uint32_t b0, uint32_t b1) {
    asm volatile(
        "mma.sync.aligned.m16n8k16.row.col.f32.bf16.bf16.f32 "
        "{%0,%1,%2,%3}, {%4,%5,%6,%7}, {%8,%9}, {%0,%1,%2,%3};"
        : "+f"(c[0]), "+f"(c[1]), "+f"(c[2]), "+f"(c[3])
        : "r"(a[0]), "r"(a[1]), "r"(a[2]), "r"(a[3]), "r"(b0), "r"(b1));
}
__device__ __forceinline__ void split_bf16(float v, __nv_bfloat16& h, __nv_bfloat16& l) {
    h = __float2bfloat16(v);
    l = __float2bfloat16(v - __bfloat162float(h));
}

// ---------------- prep kernels ----------------
__global__ void prep_A_kernel(const int* __restrict__ e, const int* __restrict__ q,
                              const float* __restrict__ H,
                              const float* __restrict__ ent_emb,
                              const float* __restrict__ rel_emb) {
    int b = blockIdx.x;
    const float* ep = ent_emb + (long)e[b] * ED_;
    const float* hp = H + (long)b * HD_;
    const float* qp = rel_emb + (long)q[b] * RD_;
    for (int i = threadIdx.x; i < XD_; i += blockDim.x) {
        float v;
        if (i < ED_)            v = ep[i];
        else if (i < ED_ + HD_) v = hp[i - ED_];
        else                    v = qp[i - ED_ - HD_];
        __nv_bfloat16 h, l;
        split_bf16(v, h, l);
        g_Ah[(long)b * XD_ + i] = h;
        g_Al[(long)b * XD_ + i] = l;
    }
}
// W [K,N] -> WT hi/lo [N,K];  WHICH 0: W1 (K=800), 1: W2 (K=400)
template<int WHICH>
__global__ void prep_WT_kernel(const float* __restrict__ W) {
    const int K = (WHICH == 0) ? XD_ : AD_;
    const int N = AD_;
    __nv_bfloat16* WTh = (WHICH == 0) ? g_W1Th : g_W2Th;
    __nv_bfloat16* WTl = (WHICH == 0) ? g_W1Tl : g_W2Tl;
    int n = blockIdx.x;
    for (int k = threadIdx.x; k < K; k += blockDim.x) {
        __nv_bfloat16 h, l;
        split_bf16(W[(long)k * N + n], h, l);
        WTh[(long)n * K + k] = h;
        WTl[(long)n * K + k] = l;
    }
}
__global__ void prep_R_kernel(const float* __restrict__ R) {
    int n = blockIdx.x;
    for (int k = threadIdx.x; k < RD_; k += blockDim.x) {
        __nv_bfloat16 h, l;
        split_bf16(R[(long)n * RD_ + k], h, l);
        g_Rh[(long)n * RD_ + k] = h;
        g_Rl[(long)n * RD_ + k] = l;
    }
}

// ---------------- warp-MMA bf16x2-compensated GEMM ----------------
// Tile: BM=64, BN=64, BK=32. 8 warps (4m x 2n), warp tile 16x32.
// 3 precision terms per fragment: Ah*Bh + Ah*Bl + Al*Bh.
// MODE 0: h1 = relu(A @ W1T^T + b1)  K=800  N=400
// MODE 1: X2 = h1 @ W2T^T + b2       K=400  N=400 (also emit X2h/l for n<200)
// MODE 2: P  = X2[:, :200] @ R^T     K=200  N=500
template<int MODE>
__global__ void __launch_bounds__(256)
mma_kernel(const float* __restrict__ bias) {
    constexpr int KREAL  = (MODE == 0) ? 800 : (MODE == 1) ? 400 : 200;
    constexpr int NN     = (MODE == 2) ? 500 : 400;
    constexpr int APITCH = KREAL;
    constexpr int BPITCH = KREAL;
    constexpr int ROWB   = 80;     // padded smem row: 40 bf16 = 80 B (conflict-free)

    __shared__ __align__(16) uint8_t smA[2][2][64 * ROWB];  // [buf][h/l]
    __shared__ __align__(16) uint8_t smB[2][2][64 * ROWB];

    const int tid  = threadIdx.x;
    const int wid  = tid >> 5;
    const int lane = tid & 31;
    const int bm = blockIdx.y * 64;
    const int bn = blockIdx.x * 64;

    const __nv_bfloat16* Ah = (MODE == 0) ? g_Ah : (MODE == 1) ? g_h1h : g_X2h;
    const __nv_bfloat16* Al = (MODE == 0) ? g_Al : (MODE == 1) ? g_h1l : g_X2l;
    const __nv_bfloat16* Bh = (MODE == 0) ? g_W1Th : (MODE == 1) ? g_W2Th : g_Rh;
    const __nv_bfloat16* Bl = (MODE == 0) ? g_W1Tl : (MODE == 1) ? g_W2Tl : g_Rl;

    // loader: thread -> (row 0..63, seg 0..3); seg = 8 bf16 = 16 B
    const int lrow = tid >> 2;
    const int lseg = tid & 3;
    const uint4 zero4 = make_uint4(0, 0, 0, 0);

    auto loadA = [&](int t, uint4& vh, uint4& vl) {
        int kg = t * 32 + lseg * 8;
        if (kg < KREAL) {
            long off = ((long)(bm + lrow) * APITCH + kg) >> 3;
            vh = reinterpret_cast<const uint4*>(Ah)[off];
            vl = reinterpret_cast<const uint4*>(Al)[off];
        } else { vh = zero4; vl = zero4; }
    };
    auto loadB = [&](int t, uint4& vh, uint4& vl) {
        int kg = t * 32 + lseg * 8;
        int n = bn + lrow;
        if (kg < KREAL && n < NN) {
            long off = ((long)n * BPITCH + kg) >> 3;
            vh = reinterpret_cast<const uint4*>(Bh)[off];
            vl = reinterpret_cast<const uint4*>(Bl)[off];
        } else { vh = zero4; vl = zero4; }
    };
    auto stage = [&](int buf, uint4 avh, uint4 avl, uint4 bvh, uint4 bvl) {
        int o = lrow * ROWB + lseg * 16;
        *reinterpret_cast<uint4*>(&smA[buf][0][o]) = avh;
        *reinterpret_cast<uint4*>(&smA[buf][1][o]) = avl;
        *reinterpret_cast<uint4*>(&smB[buf][0][o]) = bvh;
        *reinterpret_cast<uint4*>(&smB[buf][1][o]) = bvl;
    };

    // warp compute coords
    const int m0w = (wid >> 1) * 16;        // warp m offset in tile
    const int n0w = (wid & 1) * 32;         // warp n offset in tile
    const int arow = m0w + (lane & 15);     // ldmatrix A row
    const int acolb = (lane >> 4) * 16;     // ldmatrix A col byte offset (8 elems)

    float c[4][4] = {};                     // [ntile(8n)][reg]

    const int nt = (KREAL + 31) / 32;

    { uint4 avh, avl, bvh, bvl; loadA(0, avh, avl); loadB(0, bvh, bvl);
      stage(0, avh, avl, bvh, bvl); }
    __syncthreads();

    for (int t = 0; t < nt; t++) {
        const int cur = t & 1;
        uint4 pavh, pavl, pbvh, pbvl;
        const bool more = (t + 1 < nt);
        if (more) { loadA(t + 1, pavh, pavl); loadB(t + 1, pbvh, pbvl); }

        const uint32_t baseAh = smem_u32(&smA[cur][0][0]);
        const uint32_t baseAl = smem_u32(&smA[cur][1][0]);
        const uint32_t baseBh = smem_u32(&smB[cur][0][0]);
        const uint32_t baseBl = smem_u32(&smB[cur][1][0]);

        #pragma unroll
        for (int kc = 0; kc < 2; kc++) {
            const uint32_t kb = kc * 32 + acolb;   // col byte offset in row
            uint32_t ah[4], al[4];
            ldsm4(ah, baseAh + arow * ROWB + kb);
            ldsm4(al, baseAl + arow * ROWB + kb);

            #pragma unroll
            for (int np = 0; np < 2; np++) {       // pair of 8-wide n tiles
                const int brow = n0w + np * 16 + (lane & 15);
                uint32_t bh[4], bl[4];
                ldsm4(bh, baseBh + brow * ROWB + kb);
                ldsm4(bl, baseBl + brow * ROWB + kb);

                float* c0 = c[np * 2 + 0];
                float* c1 = c[np * 2 + 1];
                mma16816(c0, ah, bh[0], bh[2]);
                mma16816(c0, ah, bl[0], bl[2]);
                mma16816(c0, al, bh[0], bh[2]);
                mma16816(c1, ah, bh[1], bh[3]);
                mma16816(c1, ah, bl[1], bl[3]);
                mma16816(c1, al, bh[1], bh[3]);
            }
        }

        if (more) stage(cur ^ 1, pavh, pavl, pbvh, pbvl);
        __syncthreads();
    }

    // ---------- epilogue ----------
    const int m0 = bm + m0w;
    const int n0 = bn + n0w;
    const int r0 = m0 + (lane >> 2);
    const int r1 = r0 + 8;

    #pragma unroll
    for (int q4 = 0; q4 < 4; q4++) {
        int nc = n0 + q4 * 8 + (lane & 3) * 2;   // even column; pair (nc, nc+1)
        if (nc >= NN) continue;
        float v00 = c[q4][0], v01 = c[q4][1];    // row r0
        float v10 = c[q4][2], v11 = c[q4][3];    // row r1
        if (MODE != 2) {
            float bb0 = bias[nc], bb1 = bias[nc + 1];
            v00 += bb0; v01 += bb1; v10 += bb0; v11 += bb1;
        }
        if (MODE == 0) {
            v00 = fmaxf(v00, 0.f); v01 = fmaxf(v01, 0.f);
            v10 = fmaxf(v10, 0.f); v11 = fmaxf(v11, 0.f);
            __nv_bfloat16 h0, l0, h1, l1;
            split_bf16(v00, h0, l0); split_bf16(v01, h1, l1);
            *reinterpret_cast<__nv_bfloat162*>(&g_h1h[(long)r0 * AD_ + nc]) = __nv_bfloat162(h0, h1);
            *reinterpret_cast<__nv_bfloat162*>(&g_h1l[(long)r0 * AD_ + nc]) = __nv_bfloat162(l0, l1);
            split_bf16(v10, h0, l0); split_bf16(v11, h1, l1);
            *reinterpret_cast<__nv_bfloat162*>(&g_h1h[(long)r1 * AD_ + nc]) = __nv_bfloat162(h0, h1);
            *reinterpret_cast<__nv_bfloat162*>(&g_h1l[(long)r1 * AD_ + nc]) = __nv_bfloat162(l0, l1);
        } else if (MODE == 1) {
            *reinterpret_cast<float2*>(&g_X2[(long)r0 * AD_ + nc]) = make_float2(v00, v01);
            *reinterpret_cast<float2*>(&g_X2[(long)r1 * AD_ + nc]) = make_float2(v10, v11);
            if (nc < 200) {
                __nv_bfloat16 h0, l0, h1, l1;
                split_bf16(v00, h0, l0); split_bf16(v01, h1, l1);
                *reinterpret_cast<__nv_bfloat162*>(&g_X2h[(long)r0 * 200 + nc]) = __nv_bfloat162(h0, h1);
                *reinterpret_cast<__nv_bfloat162*>(&g_X2l[(long)r0 * 200 + nc]) = __nv_bfloat162(l0, l1);
                split_bf16(v10, h0, l0); split_bf16(v11, h1, l1);
                *reinterpret_cast<__nv_bfloat162*>(&g_X2h[(long)r1 * 200 + nc]) = __nv_bfloat162(h0, h1);
                *reinterpret_cast<__nv_bfloat162*>(&g_X2l[(long)r1 * 200 + nc]) = __nv_bfloat162(l0, l1);
            }
        } else {
            *reinterpret_cast<float2*>(&g_P[(long)r0 * NR_ + nc]) = make_float2(v00, v01);
            *reinterpret_cast<float2*>(&g_P[(long)r1 * NR_ + nc]) = make_float2(v10, v11);
        }
    }
}

// ---------------- score (R5, unchanged) ----------------
__device__ __forceinline__ float dot4(float4 a, float4 b) {
    return a.x * b.x + a.y * b.y + a.z * b.z + a.w * b.w;
}
__global__ void __launch_bounds__(256, 6)
score_kernel(const int* __restrict__ r_space,
             const int* __restrict__ e_space,
             const int* __restrict__ action_mask,
             const float* __restrict__ ent_emb,
             float* __restrict__ out_dist,
             float* __restrict__ out_ent) {
    const int b = blockIdx.x;
    const int tid = threadIdx.x;
    const int lane = tid & 31;
    const int warp = tid >> 5;
    const int grp = lane >> 3;
    const int gl = lane & 7;
    const unsigned FULL = 0xffffffffu;

    __shared__ float4 x2e[50];
    __shared__ float sc[A_];
    __shared__ float red[8];
    __shared__ unsigned char alist[8][32];

    if (tid < 50)
        x2e[tid] = reinterpret_cast<const float4*>(g_X2 + (long)b * AD_ + 200)[tid];
    sc[tid] = -1e30f;
    __syncthreads();

    const long base = (long)b * A_;
    const int aidx = warp * 32 + lane;
    const int my_r = r_space[base + aidx];
    const int my_e = e_space[base + aidx];
    const int my_m = action_mask[base + aidx];

    unsigned mbits = __ballot_sync(FULL, my_m != 0);
    const int cnt = __popc(mbits);
    if (my_m) alist[warp][__popc(mbits & ((1u << lane) - 1u))] = (unsigned char)lane;
    __syncwarp();

    const float* Prow = g_P + (long)b * NR_;

    for (int i0 = 0; i0 < cnt; i0 += 4) {
        int i = i0 + grp;
        bool act = (i < cnt);
        int sl = act ? (int)alist[warp][i] : 0;
        int rr = __shfl_sync(FULL, my_r, sl);
        int ee = __shfl_sync(FULL, my_e, sl);

        const float4* ep = reinterpret_cast<const float4*>(ent_emb + (long)ee * ED_);
        float s = 0.f;
        #pragma unroll
        for (int cc = 0; cc < 6; cc++) {
            float4 ev = ep[cc * 8 + gl];
            s += dot4(ev, x2e[cc * 8 + gl]);
        }
        if (gl < 2) {
            float4 ev = ep[48 + gl];
            s += dot4(ev, x2e[48 + gl]);
        }
        s += __shfl_xor_sync(FULL, s, 1);
        s += __shfl_xor_sync(FULL, s, 2);
        s += __shfl_xor_sync(FULL, s, 4);
        if (act && gl == 0) sc[warp * 32 + sl] = s + Prow[rr];
    }
    __syncthreads();

    float v = sc[tid];
    float mx = v;
    #pragma unroll
    for (int o = 16; o; o >>= 1) mx = fmaxf(mx, __shfl_xor_sync(FULL, mx, o));
    if (lane == 0) red[warp] = mx;
    __syncthreads();
    if (warp == 0) {
        float mm = red[lane & 7];
        #pragma unroll
        for (int o = 4; o; o >>= 1) mm = fmaxf(mm, __shfl_xor_sync(FULL, mm, o));
        if (lane == 0) red[0] = mm;
    }
    __syncthreads();
    mx = red[0];
    __syncthreads();

    float ev = expf(v - mx);
    float sm = ev;
    #pragma unroll
    for (int o = 16; o; o >>= 1) sm += __shfl_xor_sync(FULL, sm, o);
    if (lane == 0) red[warp] = sm;
    __syncthreads();
    if (warp == 0) {
        float ss = red[lane & 7];
        #pragma unroll
        for (int o = 4; o; o >>= 1) ss += __shfl_xor_sync(FULL, ss, o);
        if (lane == 0) red[0] = ss;
    }
    __syncthreads();
    float total = red[0];
    __syncthreads();

    float p = ev / total;
    out_dist[base + tid] = p;

    float t = p * logf(fmaxf(p, 1e-20f));
    float es = t;
    #pragma unroll
    for (int o = 16; o; o >>= 1) es += __shfl_xor_sync(FULL, es, o);
    if (lane == 0) red[warp] = es;
    __syncthreads();
    if (warp == 0) {
        float ss = red[lane & 7];
        #pragma unroll
        for (int o = 4; o; o >>= 1) ss += __shfl_xor_sync(FULL, ss, o);
        if (lane == 0) out_ent[b] = -ss;
    }
}

// ---------------- launch ----------------
extern "C" void kernel_launch(void* const* d_in, const int* in_sizes, int n_in,
                              void* d_out, int out_size) {
    const int*   e        = (const int*)  d_in[0];
    const int*   q        = (const int*)  d_in[1];
    const int*   r_space  = (const int*)  d_in[2];
    const int*   e_space  = (const int*)  d_in[3];
    const int*   mask     = (const int*)  d_in[4];
    const float* H        = (const float*)d_in[5];
    const float* ent_emb  = (const float*)d_in[6];
    const float* rel_emb  = (const float*)d_in[7];
    const float* W1       = (const float*)d_in[8];
    const float* b1       = (const float*)d_in[9];
    const float* W2       = (const float*)d_in[10];
    const float* b2       = (const float*)d_in[11];

    float* out_dist = (float*)d_out;
    float* out_ent  = (float*)d_out + (long)B_ * A_;

    prep_A_kernel<<<B_, 256>>>(e, q, H, ent_emb, rel_emb);
    prep_WT_kernel<0><<<AD_, 256>>>(W1);
    prep_WT_kernel<1><<<AD_, 256>>>(W2);
    prep_R_kernel<<<NR_, 256>>>(rel_emb);

    mma_kernel<0><<<dim3(7, 32), 256>>>(b1);   // 224 blocks
    mma_kernel<1><<<dim3(7, 32), 256>>>(b2);   // 224 blocks
    mma_kernel<2><<<dim3(8, 32), 256>>>(nullptr); // 256 blocks

    score_kernel<<<B_, 256>>>(r_space, e_space, mask, ent_emb,
                              out_dist, out_ent);
}

// round 8
// speedup vs baseline: 2.7888x; 1.1329x over previous
#include <cuda_runtime.h>
#include <cuda_bf16.h>
#include <math.h>
#include <stdint.h>

#define B_   2048
#define A_   256
#define ED_  200
#define RD_  200
#define HD_  400
#define XD_  800
#define AD_  400
#define NR_  500
#define HUGE_ 1e9f

// ---------------- device scratch ----------------
__device__ __nv_bfloat16 g_Ah [B_ * XD_];
__device__ __nv_bfloat16 g_Al [B_ * XD_];
__device__ __nv_bfloat16 g_h1h[B_ * AD_];
__device__ __nv_bfloat16 g_h1l[B_ * AD_];
__device__ float         g_X2 [B_ * AD_];
__device__ __nv_bfloat16 g_X2h[B_ * 200];
__device__ __nv_bfloat16 g_X2l[B_ * 200];
__device__ __nv_bfloat16 g_W1Th[AD_ * XD_];   // [400,800]
__device__ __nv_bfloat16 g_W1Tl[AD_ * XD_];
__device__ __nv_bfloat16 g_W2Th[AD_ * AD_];   // [400,400]
__device__ __nv_bfloat16 g_W2Tl[AD_ * AD_];
__device__ __nv_bfloat16 g_Rh [NR_ * RD_];    // [500,200]
__device__ __nv_bfloat16 g_Rl [NR_ * RD_];
__device__ float         g_P  [B_ * NR_];

// ---------------- helpers ----------------
__device__ __forceinline__ uint32_t smem_u32(const void* p) {
    uint32_t a;
    asm("{ .reg .u64 t; cvta.to.shared.u64 t, %1; cvt.u32.u64 %0, t; }" : "=r"(a) : "l"(p));
    return a;
}
__device__ __forceinline__ void ldsm4(uint32_t* r, uint32_t addr) {
    asm volatile("ldmatrix.sync.aligned.m8n8.x4.shared.b16 {%0,%1,%2,%3}, [%4];"
                 : "=r"(r[0]), "=r"(r[1]), "=r"(r[2]), "=r"(r[3]) : "r"(addr));
}
__device__ __forceinline__ void mma16816(float* c, const uint32_t* a,
                                         uint32_t b0, uint32_t b1) {
    asm volatile(
        "mma.sync.aligned.m16n8k16.row.col.f32.bf16.bf16.f32 "
        "{%0,%1,%2,%3}, {%4,%5,%6,%7}, {%8,%9}, {%0,%1,%2,%3};"
        : "+f"(c[0]), "+f"(c[1]), "+f"(c[2]), "+f"(c[3])
        : "r"(a[0]), "r"(a[1]), "r"(a[2]), "r"(a[3]), "r"(b0), "r"(b1));
}
__device__ __forceinline__ void split_bf16(float v, __nv_bfloat16& h, __nv_bfloat16& l) {
    h = __float2bfloat16(v);
    l = __float2bfloat16(v - __bfloat162float(h));
}

// ---------------- fused prep: one launch ----------------
// Block ranges:
//   [0, 2048)            prep_A  (b = blk)
//   [2048, 2048+325)     W1 transpose tiles (25 k-tiles x 13 n-tiles)
//   [2373, 2373+169)     W2 transpose tiles (13 x 13)
//   [2542, 2542+98)      R convert
#define PREP_A_N   B_
#define W1_KT      25
#define W1_NT      13
#define W2_KT      13
#define W2_NT      13
#define PREP_W1_N  (W1_KT * W1_NT)
#define PREP_W2_N  (W2_KT * W2_NT)
#define PREP_R_N   98
#define PREP_TOTAL (PREP_A_N + PREP_W1_N + PREP_W2_N + PREP_R_N)

__global__ void __launch_bounds__(256)
prep_all_kernel(const int* __restrict__ e, const int* __restrict__ q,
                const float* __restrict__ H,
                const float* __restrict__ ent_emb,
                const float* __restrict__ rel_emb,
                const float* __restrict__ W1,
                const float* __restrict__ W2) {
    const int blk = blockIdx.x;
    const int tid = threadIdx.x;

    if (blk < PREP_A_N) {
        // ---- A = [E|H|Q] -> bf16 hi/lo, vectorized
        const int b = blk;
        const float* ep = ent_emb + (long)e[b] * ED_;
        const float* hp = H + (long)b * HD_;
        const float* qp = rel_emb + (long)q[b] * RD_;
        const int i4 = tid * 4;
        if (i4 < XD_) {
            float4 v;
            if (i4 < ED_)            v = *reinterpret_cast<const float4*>(ep + i4);
            else if (i4 < ED_ + HD_) v = *reinterpret_cast<const float4*>(hp + (i4 - ED_));
            else                     v = *reinterpret_cast<const float4*>(qp + (i4 - ED_ - HD_));
            __nv_bfloat16 h0, l0, h1, l1, h2, l2, h3, l3;
            split_bf16(v.x, h0, l0); split_bf16(v.y, h1, l1);
            split_bf16(v.z, h2, l2); split_bf16(v.w, h3, l3);
            long o2 = ((long)b * XD_ + i4) >> 1;
            reinterpret_cast<__nv_bfloat162*>(g_Ah)[o2]     = __nv_bfloat162(h0, h1);
            reinterpret_cast<__nv_bfloat162*>(g_Ah)[o2 + 1] = __nv_bfloat162(h2, h3);
            reinterpret_cast<__nv_bfloat162*>(g_Al)[o2]     = __nv_bfloat162(l0, l1);
            reinterpret_cast<__nv_bfloat162*>(g_Al)[o2 + 1] = __nv_bfloat162(l2, l3);
        }
        return;
    }

    if (blk < PREP_A_N + PREP_W1_N + PREP_W2_N) {
        // ---- W transpose via 32x32 smem tile, hi/lo split
        __shared__ float tile[32][33];
        const bool is1 = (blk < PREP_A_N + PREP_W1_N);
        const int t = is1 ? (blk - PREP_A_N) : (blk - PREP_A_N - PREP_W1_N);
        const int K = is1 ? XD_ : AD_;
        const int N = AD_;
        const int NT = is1 ? W1_NT : W2_NT;
        const float* W = is1 ? W1 : W2;
        __nv_bfloat16* WTh = is1 ? g_W1Th : g_W2Th;
        __nv_bfloat16* WTl = is1 ? g_W1Tl : g_W2Tl;
        const int kt = t / NT, nt = t % NT;
        const int k0 = kt * 32, n0 = nt * 32;
        const int tx = tid & 31, ty = tid >> 5;   // 32 x 8

        #pragma unroll
        for (int r = 0; r < 4; r++) {
            int k = k0 + ty + r * 8;
            int n = n0 + tx;
            if (k < K && n < N) tile[ty + r * 8][tx] = W[(long)k * N + n];
        }
        __syncthreads();
        #pragma unroll
        for (int r = 0; r < 4; r++) {
            int n = n0 + ty + r * 8;
            int k = k0 + tx;
            if (k < K && n < N) {
                __nv_bfloat16 h, l;
                split_bf16(tile[tx][ty + r * 8], h, l);
                WTh[(long)n * K + k] = h;
                WTl[(long)n * K + k] = l;
            }
        }
        return;
    }

    // ---- R convert (no transpose): 500*200 floats
    {
        const int t = blk - (PREP_A_N + PREP_W1_N + PREP_W2_N);
        const int idx = (t * 256 + tid) * 4;
        if (idx < NR_ * RD_) {
            float4 v = *reinterpret_cast<const float4*>(rel_emb + idx);
            __nv_bfloat16 h0, l0, h1, l1, h2, l2, h3, l3;
            split_bf16(v.x, h0, l0); split_bf16(v.y, h1, l1);
            split_bf16(v.z, h2, l2); split_bf16(v.w, h3, l3);
            long o2 = idx >> 1;
            reinterpret_cast<__nv_bfloat162*>(g_Rh)[o2]     = __nv_bfloat162(h0, h1);
            reinterpret_cast<__nv_bfloat162*>(g_Rh)[o2 + 1] = __nv_bfloat162(h2, h3);
            reinterpret_cast<__nv_bfloat162*>(g_Rl)[o2]     = __nv_bfloat162(l0, l1);
            reinterpret_cast<__nv_bfloat162*>(g_Rl)[o2 + 1] = __nv_bfloat162(l2, l3);
        }
        return;
    }
}

// ---------------- warp-MMA bf16x2-compensated GEMM (unchanged from R7) ----------------
template<int MODE>
__global__ void __launch_bounds__(256)
mma_kernel(const float* __restrict__ bias) {
    constexpr int KREAL  = (MODE == 0) ? 800 : (MODE == 1) ? 400 : 200;
    constexpr int NN     = (MODE == 2) ? 500 : 400;
    constexpr int APITCH = KREAL;
    constexpr int BPITCH = KREAL;
    constexpr int ROWB   = 80;

    __shared__ __align__(16) uint8_t smA[2][2][64 * ROWB];
    __shared__ __align__(16) uint8_t smB[2][2][64 * ROWB];

    const int tid  = threadIdx.x;
    const int wid  = tid >> 5;
    const int lane = tid & 31;
    const int bm = blockIdx.y * 64;
    const int bn = blockIdx.x * 64;

    const __nv_bfloat16* Ah = (MODE == 0) ? g_Ah : (MODE == 1) ? g_h1h : g_X2h;
    const __nv_bfloat16* Al = (MODE == 0) ? g_Al : (MODE == 1) ? g_h1l : g_X2l;
    const __nv_bfloat16* Bh = (MODE == 0) ? g_W1Th : (MODE == 1) ? g_W2Th : g_Rh;
    const __nv_bfloat16* Bl = (MODE == 0) ? g_W1Tl : (MODE == 1) ? g_W2Tl : g_Rl;

    const int lrow = tid >> 2;
    const int lseg = tid & 3;
    const uint4 zero4 = make_uint4(0, 0, 0, 0);

    auto loadA = [&](int t, uint4& vh, uint4& vl) {
        int kg = t * 32 + lseg * 8;
        if (kg < KREAL) {
            long off = ((long)(bm + lrow) * APITCH + kg) >> 3;
            vh = reinterpret_cast<const uint4*>(Ah)[off];
            vl = reinterpret_cast<const uint4*>(Al)[off];
        } else { vh = zero4; vl = zero4; }
    };
    auto loadB = [&](int t, uint4& vh, uint4& vl) {
        int kg = t * 32 + lseg * 8;
        int n = bn + lrow;
        if (kg < KREAL && n < NN) {
            long off = ((long)n * BPITCH + kg) >> 3;
            vh = reinterpret_cast<const uint4*>(Bh)[off];
            vl = reinterpret_cast<const uint4*>(Bl)[off];
        } else { vh = zero4; vl = zero4; }
    };
    auto stage = [&](int buf, uint4 avh, uint4 avl, uint4 bvh, uint4 bvl) {
        int o = lrow * ROWB + lseg * 16;
        *reinterpret_cast<uint4*>(&smA[buf][0][o]) = avh;
        *reinterpret_cast<uint4*>(&smA[buf][1][o]) = avl;
        *reinterpret_cast<uint4*>(&smB[buf][0][o]) = bvh;
        *reinterpret_cast<uint4*>(&smB[buf][1][o]) = bvl;
    };

    const int m0w = (wid >> 1) * 16;
    const int n0w = (wid & 1) * 32;
    const int arow = m0w + (lane & 15);
    const int acolb = (lane >> 4) * 16;

    float c[4][4] = {};
    const int nt = (KREAL + 31) / 32;

    { uint4 avh, avl, bvh, bvl; loadA(0, avh, avl); loadB(0, bvh, bvl);
      stage(0, avh, avl, bvh, bvl); }
    __syncthreads();

    for (int t = 0; t < nt; t++) {
        const int cur = t & 1;
        uint4 pavh, pavl, pbvh, pbvl;
        const bool more = (t + 1 < nt);
        if (more) { loadA(t + 1, pavh, pavl); loadB(t + 1, pbvh, pbvl); }

        const uint32_t baseAh = smem_u32(&smA[cur][0][0]);
        const uint32_t baseAl = smem_u32(&smA[cur][1][0]);
        const uint32_t baseBh = smem_u32(&smB[cur][0][0]);
        const uint32_t baseBl = smem_u32(&smB[cur][1][0]);

        #pragma unroll
        for (int kc = 0; kc < 2; kc++) {
            const uint32_t kb = kc * 32 + acolb;
            uint32_t ah[4], al[4];
            ldsm4(ah, baseAh + arow * ROWB + kb);
            ldsm4(al, baseAl + arow * ROWB + kb);

            #pragma unroll
            for (int np = 0; np < 2; np++) {
                const int brow = n0w + np * 16 + (lane & 15);
                uint32_t bh[4], bl[4];
                ldsm4(bh, baseBh + brow * ROWB + kb);
                ldsm4(bl, baseBl + brow * ROWB + kb);

                float* c0 = c[np * 2 + 0];
                float* c1 = c[np * 2 + 1];
                mma16816(c0, ah, bh[0], bh[2]);
                mma16816(c0, ah, bl[0], bl[2]);
                mma16816(c0, al, bh[0], bh[2]);
                mma16816(c1, ah, bh[1], bh[3]);
                mma16816(c1, ah, bl[1], bl[3]);
                mma16816(c1, al, bh[1], bh[3]);
            }
        }

        if (more) stage(cur ^ 1, pavh, pavl, pbvh, pbvl);
        __syncthreads();
    }

    const int m0 = bm + m0w;
    const int n0 = bn + n0w;
    const int r0 = m0 + (lane >> 2);
    const int r1 = r0 + 8;

    #pragma unroll
    for (int q4 = 0; q4 < 4; q4++) {
        int nc = n0 + q4 * 8 + (lane & 3) * 2;
        if (nc >= NN) continue;
        float v00 = c[q4][0], v01 = c[q4][1];
        float v10 = c[q4][2], v11 = c[q4][3];
        if (MODE != 2) {
            float bb0 = bias[nc], bb1 = bias[nc + 1];
            v00 += bb0; v01 += bb1; v10 += bb0; v11 += bb1;
        }
        if (MODE == 0) {
            v00 = fmaxf(v00, 0.f); v01 = fmaxf(v01, 0.f);
            v10 = fmaxf(v10, 0.f); v11 = fmaxf(v11, 0.f);
            __nv_bfloat16 h0, l0, h1, l1;
            split_bf16(v00, h0, l0); split_bf16(v01, h1, l1);
            *reinterpret_cast<__nv_bfloat162*>(&g_h1h[(long)r0 * AD_ + nc]) = __nv_bfloat162(h0, h1);
            *reinterpret_cast<__nv_bfloat162*>(&g_h1l[(long)r0 * AD_ + nc]) = __nv_bfloat162(l0, l1);
            split_bf16(v10, h0, l0); split_bf16(v11, h1, l1);
            *reinterpret_cast<__nv_bfloat162*>(&g_h1h[(long)r1 * AD_ + nc]) = __nv_bfloat162(h0, h1);
            *reinterpret_cast<__nv_bfloat162*>(&g_h1l[(long)r1 * AD_ + nc]) = __nv_bfloat162(l0, l1);
        } else if (MODE == 1) {
            *reinterpret_cast<float2*>(&g_X2[(long)r0 * AD_ + nc]) = make_float2(v00, v01);
            *reinterpret_cast<float2*>(&g_X2[(long)r1 * AD_ + nc]) = make_float2(v10, v11);
            if (nc < 200) {
                __nv_bfloat16 h0, l0, h1, l1;
                split_bf16(v00, h0, l0); split_bf16(v01, h1, l1);
                *reinterpret_cast<__nv_bfloat162*>(&g_X2h[(long)r0 * 200 + nc]) = __nv_bfloat162(h0, h1);
                *reinterpret_cast<__nv_bfloat162*>(&g_X2l[(long)r0 * 200 + nc]) = __nv_bfloat162(l0, l1);
                split_bf16(v10, h0, l0); split_bf16(v11, h1, l1);
                *reinterpret_cast<__nv_bfloat162*>(&g_X2h[(long)r1 * 200 + nc]) = __nv_bfloat162(h0, h1);
                *reinterpret_cast<__nv_bfloat162*>(&g_X2l[(long)r1 * 200 + nc]) = __nv_bfloat162(l0, l1);
            }
        } else {
            *reinterpret_cast<float2*>(&g_P[(long)r0 * NR_ + nc]) = make_float2(v00, v01);
            *reinterpret_cast<float2*>(&g_P[(long)r1 * NR_ + nc]) = make_float2(v10, v11);
        }
    }
}

// ---------------- score ----------------
__device__ __forceinline__ float dot4(float4 a, float4 b) {
    return a.x * b.x + a.y * b.y + a.z * b.z + a.w * b.w;
}
__global__ void __launch_bounds__(256, 8)
score_kernel(const int* __restrict__ r_space,
             const int* __restrict__ e_space,
             const int* __restrict__ action_mask,
             const float* __restrict__ ent_emb,
             float* __restrict__ out_dist,
             float* __restrict__ out_ent) {
    const int b = blockIdx.x;
    const int tid = threadIdx.x;
    const int lane = tid & 31;
    const int warp = tid >> 5;
    const int grp = lane >> 3;
    const int gl = lane & 7;
    const unsigned FULL = 0xffffffffu;

    __shared__ float4 x2e[50];
    __shared__ float sc[A_];
    __shared__ float red[8];
    __shared__ unsigned char alist[8][32];

    if (tid < 50)
        x2e[tid] = reinterpret_cast<const float4*>(g_X2 + (long)b * AD_ + 200)[tid];
    sc[tid] = -1e30f;
    __syncthreads();

    const long base = (long)b * A_;
    const int aidx = warp * 32 + lane;
    const int my_r = r_space[base + aidx];
    const int my_e = e_space[base + aidx];
    const int my_m = action_mask[base + aidx];

    unsigned mbits = __ballot_sync(FULL, my_m != 0);
    const int cnt = __popc(mbits);
    if (my_m) alist[warp][__popc(mbits & ((1u << lane) - 1u))] = (unsigned char)lane;
    __syncwarp();

    const float* Prow = g_P + (long)b * NR_;

    for (int i0 = 0; i0 < cnt; i0 += 4) {
        int i = i0 + grp;
        bool act = (i < cnt);
        int sl = act ? (int)alist[warp][i] : 0;
        int rr = __shfl_sync(FULL, my_r, sl);
        int ee = __shfl_sync(FULL, my_e, sl);

        const float4* ep = reinterpret_cast<const float4*>(ent_emb + (long)ee * ED_);
        float s = 0.f;
        #pragma unroll
        for (int cc = 0; cc < 6; cc++) {
            float4 ev = ep[cc * 8 + gl];
            s += dot4(ev, x2e[cc * 8 + gl]);
        }
        if (gl < 2) {
            float4 ev = ep[48 + gl];
            s += dot4(ev, x2e[48 + gl]);
        }
        s += __shfl_xor_sync(FULL, s, 1);
        s += __shfl_xor_sync(FULL, s, 2);
        s += __shfl_xor_sync(FULL, s, 4);
        if (act && gl == 0) sc[warp * 32 + sl] = s + Prow[rr];
    }
    __syncthreads();

    float v = sc[tid];
    float mx = v;
    #pragma unroll
    for (int o = 16; o; o >>= 1) mx = fmaxf(mx, __shfl_xor_sync(FULL, mx, o));
    if (lane == 0) red[warp] = mx;
    __syncthreads();
    if (warp == 0) {
        float mm = red[lane & 7];
        #pragma unroll
        for (int o = 4; o; o >>= 1) mm = fmaxf(mm, __shfl_xor_sync(FULL, mm, o));
        if (lane == 0) red[0] = mm;
    }
    __syncthreads();
    mx = red[0];
    __syncthreads();

    float ev = expf(v - mx);
    float sm = ev;
    #pragma unroll
    for (int o = 16; o; o >>= 1) sm += __shfl_xor_sync(FULL, sm, o);
    if (lane == 0) red[warp] = sm;
    __syncthreads();
    if (warp == 0) {
        float ss = red[lane & 7];
        #pragma unroll
        for (int o = 4; o; o >>= 1) ss += __shfl_xor_sync(FULL, ss, o);
        if (lane == 0) red[0] = ss;
    }
    __syncthreads();
    float total = red[0];
    __syncthreads();

    float p = ev / total;
    out_dist[base + tid] = p;

    float t = p * logf(fmaxf(p, 1e-20f));
    float es = t;
    #pragma unroll
    for (int o = 16; o; o >>= 1) es += __shfl_xor_sync(FULL, es, o);
    if (lane == 0) red[warp] = es;
    __syncthreads();
    if (warp == 0) {
        float ss = red[lane & 7];
        #pragma unroll
        for (int o = 4; o; o >>= 1) ss += __shfl_xor_sync(FULL, ss, o);
        if (lane == 0) out_ent[b] = -ss;
    }
}

// ---------------- launch ----------------
extern "C" void kernel_launch(void* const* d_in, const int* in_sizes, int n_in,
                              void* d_out, int out_size) {
    const int*   e        = (const int*)  d_in[0];
    const int*   q        = (const int*)  d_in[1];
    const int*   r_space  = (const int*)  d_in[2];
    const int*   e_space  = (const int*)  d_in[3];
    const int*   mask     = (const int*)  d_in[4];
    const float* H        = (const float*)d_in[5];
    const float* ent_emb  = (const float*)d_in[6];
    const float* rel_emb  = (const float*)d_in[7];
    const float* W1       = (const float*)d_in[8];
    const float* b1       = (const float*)d_in[9];
    const float* W2       = (const float*)d_in[10];
    const float* b2       = (const float*)d_in[11];

    float* out_dist = (float*)d_out;
    float* out_ent  = (float*)d_out + (long)B_ * A_;

    prep_all_kernel<<<PREP_TOTAL, 256>>>(e, q, H, ent_emb, rel_emb, W1, W2);

    mma_kernel<0><<<dim3(7, 32), 256>>>(b1);
    mma_kernel<1><<<dim3(7, 32), 256>>>(b2);
    mma_kernel<2><<<dim3(8, 32), 256>>>(nullptr);

    score_kernel<<<B_, 256>>>(r_space, e_space, mask, ent_emb,
                              out_dist, out_ent);
}

// round 9
// speedup vs baseline: 2.8054x; 1.0059x over previous
#include <cuda_runtime.h>
#include <cuda_bf16.h>
#include <math.h>
#include <stdint.h>

#define B_   2048
#define A_   256
#define ED_  200
#define RD_  200
#define HD_  400
#define XD_  800
#define AD_  400
#define NR_  500
#define HUGE_ 1e9f

// ---------------- device scratch ----------------
__device__ __nv_bfloat16 g_Ah [B_ * XD_];
__device__ __nv_bfloat16 g_Al [B_ * XD_];
__device__ __nv_bfloat16 g_h1h[B_ * AD_];
__device__ __nv_bfloat16 g_h1l[B_ * AD_];
__device__ float         g_X2 [B_ * AD_];
__device__ __nv_bfloat16 g_X2h[B_ * 200];
__device__ __nv_bfloat16 g_X2l[B_ * 200];
__device__ __nv_bfloat16 g_W1Th[AD_ * XD_];
__device__ __nv_bfloat16 g_W1Tl[AD_ * XD_];
__device__ __nv_bfloat16 g_W2Th[AD_ * AD_];
__device__ __nv_bfloat16 g_W2Tl[AD_ * AD_];
__device__ __nv_bfloat16 g_Rh [NR_ * RD_];
__device__ __nv_bfloat16 g_Rl [NR_ * RD_];
__device__ float         g_P  [B_ * NR_];

// ---------------- helpers ----------------
__device__ __forceinline__ uint32_t smem_u32(const void* p) {
    uint32_t a;
    asm("{ .reg .u64 t; cvta.to.shared.u64 t, %1; cvt.u32.u64 %0, t; }" : "=r"(a) : "l"(p));
    return a;
}
__device__ __forceinline__ void ldsm4(uint32_t* r, uint32_t addr) {
    asm volatile("ldmatrix.sync.aligned.m8n8.x4.shared.b16 {%0,%1,%2,%3}, [%4];"
                 : "=r"(r[0]), "=r"(r[1]), "=r"(r[2]), "=r"(r[3]) : "r"(addr));
}
__device__ __forceinline__ void mma16816(float* c, const uint32_t* a,
                                         uint32_t b0, uint32_t b1) {
    asm volatile(
        "mma.sync.aligned.m16n8k16.row.col.f32.bf16.bf16.f32 "
        "{%0,%1,%2,%3}, {%4,%5,%6,%7}, {%8,%9}, {%0,%1,%2,%3};"
        : "+f"(c[0]), "+f"(c[1]), "+f"(c[2]), "+f"(c[3])
        : "r"(a[0]), "r"(a[1]), "r"(a[2]), "r"(a[3]), "r"(b0), "r"(b1));
}
__device__ __forceinline__ void split_bf16(float v, __nv_bfloat16& h, __nv_bfloat16& l) {
    h = __float2bfloat16(v);
    l = __float2bfloat16(v - __bfloat162float(h));
}
__device__ __forceinline__ void cpasync16(uint32_t dst, const void* src, int sz) {
    asm volatile("cp.async.cg.shared.global [%0], [%1], 16, %2;"
                 :: "r"(dst), "l"(src), "r"(sz) : "memory");
}
#define CP_COMMIT() asm volatile("cp.async.commit_group;" ::: "memory")
#define CP_WAIT0()  asm volatile("cp.async.wait_group 0;" ::: "memory")
#define CP_WAIT1()  asm volatile("cp.async.wait_group 1;" ::: "memory")

// ---------------- fused prep (unchanged from R8) ----------------
#define PREP_A_N   B_
#define W1_KT      25
#define W1_NT      13
#define W2_KT      13
#define W2_NT      13
#define PREP_W1_N  (W1_KT * W1_NT)
#define PREP_W2_N  (W2_KT * W2_NT)
#define PREP_R_N   98
#define PREP_TOTAL (PREP_A_N + PREP_W1_N + PREP_W2_N + PREP_R_N)

__global__ void __launch_bounds__(256)
prep_all_kernel(const int* __restrict__ e, const int* __restrict__ q,
                const float* __restrict__ H,
                const float* __restrict__ ent_emb,
                const float* __restrict__ rel_emb,
                const float* __restrict__ W1,
                const float* __restrict__ W2) {
    const int blk = blockIdx.x;
    const int tid = threadIdx.x;

    if (blk < PREP_A_N) {
        const int b = blk;
        const float* ep = ent_emb + (long)e[b] * ED_;
        const float* hp = H + (long)b * HD_;
        const float* qp = rel_emb + (long)q[b] * RD_;
        const int i4 = tid * 4;
        if (i4 < XD_) {
            float4 v;
            if (i4 < ED_)            v = *reinterpret_cast<const float4*>(ep + i4);
            else if (i4 < ED_ + HD_) v = *reinterpret_cast<const float4*>(hp + (i4 - ED_));
            else                     v = *reinterpret_cast<const float4*>(qp + (i4 - ED_ - HD_));
            __nv_bfloat16 h0, l0, h1, l1, h2, l2, h3, l3;
            split_bf16(v.x, h0, l0); split_bf16(v.y, h1, l1);
            split_bf16(v.z, h2, l2); split_bf16(v.w, h3, l3);
            long o2 = ((long)b * XD_ + i4) >> 1;
            reinterpret_cast<__nv_bfloat162*>(g_Ah)[o2]     = __nv_bfloat162(h0, h1);
            reinterpret_cast<__nv_bfloat162*>(g_Ah)[o2 + 1] = __nv_bfloat162(h2, h3);
            reinterpret_cast<__nv_bfloat162*>(g_Al)[o2]     = __nv_bfloat162(l0, l1);
            reinterpret_cast<__nv_bfloat162*>(g_Al)[o2 + 1] = __nv_bfloat162(l2, l3);
        }
        return;
    }

    if (blk < PREP_A_N + PREP_W1_N + PREP_W2_N) {
        __shared__ float tile[32][33];
        const bool is1 = (blk < PREP_A_N + PREP_W1_N);
        const int t = is1 ? (blk - PREP_A_N) : (blk - PREP_A_N - PREP_W1_N);
        const int K = is1 ? XD_ : AD_;
        const int N = AD_;
        const int NT = is1 ? W1_NT : W2_NT;
        const float* W = is1 ? W1 : W2;
        __nv_bfloat16* WTh = is1 ? g_W1Th : g_W2Th;
        __nv_bfloat16* WTl = is1 ? g_W1Tl : g_W2Tl;
        const int kt = t / NT, nt = t % NT;
        const int k0 = kt * 32, n0 = nt * 32;
        const int tx = tid & 31, ty = tid >> 5;

        #pragma unroll
        for (int r = 0; r < 4; r++) {
            int k = k0 + ty + r * 8;
            int n = n0 + tx;
            if (k < K && n < N) tile[ty + r * 8][tx] = W[(long)k * N + n];
        }
        __syncthreads();
        #pragma unroll
        for (int r = 0; r < 4; r++) {
            int n = n0 + ty + r * 8;
            int k = k0 + tx;
            if (k < K && n < N) {
                __nv_bfloat16 h, l;
                split_bf16(tile[tx][ty + r * 8], h, l);
                WTh[(long)n * K + k] = h;
                WTl[(long)n * K + k] = l;
            }
        }
        return;
    }

    {
        const int t = blk - (PREP_A_N + PREP_W1_N + PREP_W2_N);
        const int idx = (t * 256 + tid) * 4;
        if (idx < NR_ * RD_) {
            float4 v = *reinterpret_cast<const float4*>(rel_emb + idx);
            __nv_bfloat16 h0, l0, h1, l1, h2, l2, h3, l3;
            split_bf16(v.x, h0, l0); split_bf16(v.y, h1, l1);
            split_bf16(v.z, h2, l2); split_bf16(v.w, h3, l3);
            long o2 = idx >> 1;
            reinterpret_cast<__nv_bfloat162*>(g_Rh)[o2]     = __nv_bfloat162(h0, h1);
            reinterpret_cast<__nv_bfloat162*>(g_Rh)[o2 + 1] = __nv_bfloat162(h2, h3);
            reinterpret_cast<__nv_bfloat162*>(g_Rl)[o2]     = __nv_bfloat162(l0, l1);
            reinterpret_cast<__nv_bfloat162*>(g_Rl)[o2 + 1] = __nv_bfloat162(l2, l3);
        }
        return;
    }
}

// ---------------- warp-MMA GEMM: BK=64, cp.async 2-stage ----------------
// Tile BM=64, BN=64. 8 warps (4m x 2n), warp tile 16x32.
// smem row = 64 bf16 = 128 B, padded to 144 B (conflict-free ldmatrix).
// Dynamic smem layout (byte offsets from base):
//   A_h: buf*9216            (2 bufs, 18432)
//   A_l: 18432 + buf*9216
//   B_h: 36864 + buf*9216
//   B_l: 55296 + buf*9216    total 73728
#define ROWB  144
#define BUFSZ (64 * ROWB)       // 9216
#define OFF_AH 0
#define OFF_AL (2 * BUFSZ)
#define OFF_BH (4 * BUFSZ)
#define OFF_BL (6 * BUFSZ)
#define MMA_SMEM (8 * BUFSZ)    // 73728

template<int MODE>
__global__ void __launch_bounds__(256)
mma_kernel(const float* __restrict__ bias) {
    constexpr int KREAL = (MODE == 0) ? 800 : (MODE == 1) ? 400 : 200;
    constexpr int NN    = (MODE == 2) ? 500 : 400;
    constexpr int NT    = (KREAL + 63) / 64;

    extern __shared__ __align__(16) uint8_t dyn[];
    const uint32_t sb = smem_u32(dyn);

    const int tid  = threadIdx.x;
    const int wid  = tid >> 5;
    const int lane = tid & 31;
    const int bm = blockIdx.y * 64;
    const int bn = blockIdx.x * 64;

    const __nv_bfloat16* Ah = (MODE == 0) ? g_Ah : (MODE == 1) ? g_h1h : g_X2h;
    const __nv_bfloat16* Al = (MODE == 0) ? g_Al : (MODE == 1) ? g_h1l : g_X2l;
    const __nv_bfloat16* Bh = (MODE == 0) ? g_W1Th : (MODE == 1) ? g_W2Th : g_Rh;
    const __nv_bfloat16* Bl = (MODE == 0) ? g_W1Tl : (MODE == 1) ? g_W2Tl : g_Rl;

    const int lrow = tid >> 2;          // 0..63
    const int lseg0 = tid & 3;          // segs lseg0, lseg0+4
    const int nrow = bn + lrow;
    const bool nok = (nrow < NN);

    auto issue = [&](int t, int buf) {
        const uint32_t so_base = (uint32_t)buf * BUFSZ + lrow * ROWB;
        #pragma unroll
        for (int ss = 0; ss < 2; ss++) {
            const int seg = lseg0 + ss * 4;
            const int kg = t * 64 + seg * 8;
            const bool kok = (kg < KREAL);
            const int kcl = kok ? kg : 0;
            const uint32_t so = so_base + seg * 16;
            const long aoff = (long)(bm + lrow) * KREAL + kcl;
            const long boff = (long)(nok ? nrow : 0) * KREAL + kcl;
            const int szA = kok ? 16 : 0;
            const int szB = (kok && nok) ? 16 : 0;
            cpasync16(sb + OFF_AH + so, Ah + aoff, szA);
            cpasync16(sb + OFF_AL + so, Al + aoff, szA);
            cpasync16(sb + OFF_BH + so, Bh + boff, szB);
            cpasync16(sb + OFF_BL + so, Bl + boff, szB);
        }
    };

    const int m0w = (wid >> 1) * 16;
    const int n0w = (wid & 1) * 32;
    const int arow = m0w + (lane & 15);
    const int acolb = (lane >> 4) * 16;

    float c[4][4] = {};

    issue(0, 0);
    CP_COMMIT();

    for (int t = 0; t < NT; t++) {
        const int cur = t & 1;
        if (t + 1 < NT) { issue(t + 1, cur ^ 1); CP_COMMIT(); CP_WAIT1(); }
        else            { CP_WAIT0(); }
        __syncthreads();

        const uint32_t bAh = sb + OFF_AH + cur * BUFSZ;
        const uint32_t bAl = sb + OFF_AL + cur * BUFSZ;
        const uint32_t bBh = sb + OFF_BH + cur * BUFSZ;
        const uint32_t bBl = sb + OFF_BL + cur * BUFSZ;

        #pragma unroll
        for (int kc = 0; kc < 4; kc++) {
            const uint32_t kb = kc * 32 + acolb;
            uint32_t ah[4], al[4];
            ldsm4(ah, bAh + arow * ROWB + kb);
            ldsm4(al, bAl + arow * ROWB + kb);

            #pragma unroll
            for (int np = 0; np < 2; np++) {
                const int brow = n0w + np * 16 + (lane & 15);
                uint32_t bh[4], bl[4];
                ldsm4(bh, bBh + brow * ROWB + kb);
                ldsm4(bl, bBl + brow * ROWB + kb);

                float* c0 = c[np * 2 + 0];
                float* c1 = c[np * 2 + 1];
                mma16816(c0, ah, bh[0], bh[2]);
                mma16816(c0, ah, bl[0], bl[2]);
                mma16816(c0, al, bh[0], bh[2]);
                mma16816(c1, ah, bh[1], bh[3]);
                mma16816(c1, ah, bl[1], bl[3]);
                mma16816(c1, al, bh[1], bh[3]);
            }
        }
        __syncthreads();
    }

    // ---------- epilogue ----------
    const int m0 = bm + m0w;
    const int n0 = bn + n0w;
    const int r0 = m0 + (lane >> 2);
    const int r1 = r0 + 8;

    #pragma unroll
    for (int q4 = 0; q4 < 4; q4++) {
        int nc = n0 + q4 * 8 + (lane & 3) * 2;
        if (nc >= NN) continue;
        float v00 = c[q4][0], v01 = c[q4][1];
        float v10 = c[q4][2], v11 = c[q4][3];
        if (MODE != 2) {
            float bb0 = bias[nc], bb1 = bias[nc + 1];
            v00 += bb0; v01 += bb1; v10 += bb0; v11 += bb1;
        }
        if (MODE == 0) {
            v00 = fmaxf(v00, 0.f); v01 = fmaxf(v01, 0.f);
            v10 = fmaxf(v10, 0.f); v11 = fmaxf(v11, 0.f);
            __nv_bfloat16 h0, l0, h1, l1;
            split_bf16(v00, h0, l0); split_bf16(v01, h1, l1);
            *reinterpret_cast<__nv_bfloat162*>(&g_h1h[(long)r0 * AD_ + nc]) = __nv_bfloat162(h0, h1);
            *reinterpret_cast<__nv_bfloat162*>(&g_h1l[(long)r0 * AD_ + nc]) = __nv_bfloat162(l0, l1);
            split_bf16(v10, h0, l0); split_bf16(v11, h1, l1);
            *reinterpret_cast<__nv_bfloat162*>(&g_h1h[(long)r1 * AD_ + nc]) = __nv_bfloat162(h0, h1);
            *reinterpret_cast<__nv_bfloat162*>(&g_h1l[(long)r1 * AD_ + nc]) = __nv_bfloat162(l0, l1);
        } else if (MODE == 1) {
            *reinterpret_cast<float2*>(&g_X2[(long)r0 * AD_ + nc]) = make_float2(v00, v01);
            *reinterpret_cast<float2*>(&g_X2[(long)r1 * AD_ + nc]) = make_float2(v10, v11);
            if (nc < 200) {
                __nv_bfloat16 h0, l0, h1, l1;
                split_bf16(v00, h0, l0); split_bf16(v01, h1, l1);
                *reinterpret_cast<__nv_bfloat162*>(&g_X2h[(long)r0 * 200 + nc]) = __nv_bfloat162(h0, h1);
                *reinterpret_cast<__nv_bfloat162*>(&g_X2l[(long)r0 * 200 + nc]) = __nv_bfloat162(l0, l1);
                split_bf16(v10, h0, l0); split_bf16(v11, h1, l1);
                *reinterpret_cast<__nv_bfloat162*>(&g_X2h[(long)r1 * 200 + nc]) = __nv_bfloat162(h0, h1);
                *reinterpret_cast<__nv_bfloat162*>(&g_X2l[(long)r1 * 200 + nc]) = __nv_bfloat162(l0, l1);
            }
        } else {
            *reinterpret_cast<float2*>(&g_P[(long)r0 * NR_ + nc]) = make_float2(v00, v01);
            *reinterpret_cast<float2*>(&g_P[(long)r1 * NR_ + nc]) = make_float2(v10, v11);
        }
    }
}

// ---------------- score (unchanged from R8) ----------------
__device__ __forceinline__ float dot4(float4 a, float4 b) {
    return a.x * b.x + a.y * b.y + a.z * b.z + a.w * b.w;
}
__global__ void __launch_bounds__(256, 8)
score_kernel(const int* __restrict__ r_space,
             const int* __restrict__ e_space,
             const int* __restrict__ action_mask,
             const float* __restrict__ ent_emb,
             float* __restrict__ out_dist,
             float* __restrict__ out_ent) {
    const int b = blockIdx.x;
    const int tid = threadIdx.x;
    const int lane = tid & 31;
    const int warp = tid >> 5;
    const int grp = lane >> 3;
    const int gl = lane & 7;
    const unsigned FULL = 0xffffffffu;

    __shared__ float4 x2e[50];
    __shared__ float sc[A_];
    __shared__ float red[8];
    __shared__ unsigned char alist[8][32];

    if (tid < 50)
        x2e[tid] = reinterpret_cast<const float4*>(g_X2 + (long)b * AD_ + 200)[tid];
    sc[tid] = -1e30f;
    __syncthreads();

    const long base = (long)b * A_;
    const int aidx = warp * 32 + lane;
    const int my_r = r_space[base + aidx];
    const int my_e = e_space[base + aidx];
    const int my_m = action_mask[base + aidx];

    unsigned mbits = __ballot_sync(FULL, my_m != 0);
    const int cnt = __popc(mbits);
    if (my_m) alist[warp][__popc(mbits & ((1u << lane) - 1u))] = (unsigned char)lane;
    __syncwarp();

    const float* Prow = g_P + (long)b * NR_;

    for (int i0 = 0; i0 < cnt; i0 += 4) {
        int i = i0 + grp;
        bool act = (i < cnt);
        int sl = act ? (int)alist[warp][i] : 0;
        int rr = __shfl_sync(FULL, my_r, sl);
        int ee = __shfl_sync(FULL, my_e, sl);

        const float4* ep = reinterpret_cast<const float4*>(ent_emb + (long)ee * ED_);
        float s = 0.f;
        #pragma unroll
        for (int cc = 0; cc < 6; cc++) {
            float4 ev = ep[cc * 8 + gl];
            s += dot4(ev, x2e[cc * 8 + gl]);
        }
        if (gl < 2) {
            float4 ev = ep[48 + gl];
            s += dot4(ev, x2e[48 + gl]);
        }
        s += __shfl_xor_sync(FULL, s, 1);
        s += __shfl_xor_sync(FULL, s, 2);
        s += __shfl_xor_sync(FULL, s, 4);
        if (act && gl == 0) sc[warp * 32 + sl] = s + Prow[rr];
    }
    __syncthreads();

    float v = sc[tid];
    float mx = v;
    #pragma unroll
    for (int o = 16; o; o >>= 1) mx = fmaxf(mx, __shfl_xor_sync(FULL, mx, o));
    if (lane == 0) red[warp] = mx;
    __syncthreads();
    if (warp == 0) {
        float mm = red[lane & 7];
        #pragma unroll
        for (int o = 4; o; o >>= 1) mm = fmaxf(mm, __shfl_xor_sync(FULL, mm, o));
        if (lane == 0) red[0] = mm;
    }
    __syncthreads();
    mx = red[0];
    __syncthreads();

    float ev = expf(v - mx);
    float sm = ev;
    #pragma unroll
    for (int o = 16; o; o >>= 1) sm += __shfl_xor_sync(FULL, sm, o);
    if (lane == 0) red[warp] = sm;
    __syncthreads();
    if (warp == 0) {
        float ss = red[lane & 7];
        #pragma unroll
        for (int o = 4; o; o >>= 1) ss += __shfl_xor_sync(FULL, ss, o);
        if (lane == 0) red[0] = ss;
    }
    __syncthreads();
    float total = red[0];
    __syncthreads();

    float p = ev / total;
    out_dist[base + tid] = p;

    float t = p * logf(fmaxf(p, 1e-20f));
    float es = t;
    #pragma unroll
    for (int o = 16; o; o >>= 1) es += __shfl_xor_sync(FULL, es, o);
    if (lane == 0) red[warp] = es;
    __syncthreads();
    if (warp == 0) {
        float ss = red[lane & 7];
        #pragma unroll
        for (int o = 4; o; o >>= 1) ss += __shfl_xor_sync(FULL, ss, o);
        if (lane == 0) out_ent[b] = -ss;
    }
}

// ---------------- launch ----------------
extern "C" void kernel_launch(void* const* d_in, const int* in_sizes, int n_in,
                              void* d_out, int out_size) {
    const int*   e        = (const int*)  d_in[0];
    const int*   q        = (const int*)  d_in[1];
    const int*   r_space  = (const int*)  d_in[2];
    const int*   e_space  = (const int*)  d_in[3];
    const int*   mask     = (const int*)  d_in[4];
    const float* H        = (const float*)d_in[5];
    const float* ent_emb  = (const float*)d_in[6];
    const float* rel_emb  = (const float*)d_in[7];
    const float* W1       = (const float*)d_in[8];
    const float* b1       = (const float*)d_in[9];
    const float* W2       = (const float*)d_in[10];
    const float* b2       = (const float*)d_in[11];

    float* out_dist = (float*)d_out;
    float* out_ent  = (float*)d_out + (long)B_ * A_;

    cudaFuncSetAttribute(mma_kernel<0>, cudaFuncAttributeMaxDynamicSharedMemorySize, MMA_SMEM);
    cudaFuncSetAttribute(mma_kernel<1>, cudaFuncAttributeMaxDynamicSharedMemorySize, MMA_SMEM);
    cudaFuncSetAttribute(mma_kernel<2>, cudaFuncAttributeMaxDynamicSharedMemorySize, MMA_SMEM);

    prep_all_kernel<<<PREP_TOTAL, 256>>>(e, q, H, ent_emb, rel_emb, W1, W2);

    mma_kernel<0><<<dim3(7, 32), 256, MMA_SMEM>>>(b1);
    mma_kernel<1><<<dim3(7, 32), 256, MMA_SMEM>>>(b2);
    mma_kernel<2><<<dim3(8, 32), 256, MMA_SMEM>>>(nullptr);

    score_kernel<<<B_, 256>>>(r_space, e_space, mask, ent_emb,
                              out_dist, out_ent);
}

// round 10
// speedup vs baseline: 3.1878x; 1.1363x over previous
#include <cuda_runtime.h>
#include <cuda_bf16.h>
#include <math.h>
#include <stdint.h>

#define B_   2048
#define A_   256
#define ED_  200
#define RD_  200
#define HD_  400
#define XD_  800
#define AD_  400
#define NR_  500
#define HUGE_ 1e9f

// ---------------- device scratch ----------------
__device__ __nv_bfloat16 g_Ah [B_ * XD_];
__device__ __nv_bfloat16 g_Al [B_ * XD_];
__device__ __nv_bfloat16 g_h1h[B_ * AD_];
__device__ __nv_bfloat16 g_h1l[B_ * AD_];
__device__ float         g_X2 [B_ * AD_];
__device__ __nv_bfloat16 g_X2h[B_ * 200];
__device__ __nv_bfloat16 g_X2l[B_ * 200];
__device__ __nv_bfloat16 g_W1Th[AD_ * XD_];
__device__ __nv_bfloat16 g_W1Tl[AD_ * XD_];
__device__ __nv_bfloat16 g_W2Th[AD_ * AD_];
__device__ __nv_bfloat16 g_W2Tl[AD_ * AD_];
__device__ __nv_bfloat16 g_Rh [NR_ * RD_];
__device__ __nv_bfloat16 g_Rl [NR_ * RD_];
__device__ float         g_P  [B_ * NR_];

// ---------------- helpers ----------------
__device__ __forceinline__ uint32_t smem_u32(const void* p) {
    uint32_t a;
    asm("{ .reg .u64 t; cvta.to.shared.u64 t, %1; cvt.u32.u64 %0, t; }" : "=r"(a) : "l"(p));
    return a;
}
#define SW128(x) ((x) ^ (((x) >> 3) & 0x70))
__device__ __forceinline__ void ldsm4(uint32_t* r, uint32_t addr) {
    asm volatile("ldmatrix.sync.aligned.m8n8.x4.shared.b16 {%0,%1,%2,%3}, [%4];"
                 : "=r"(r[0]), "=r"(r[1]), "=r"(r[2]), "=r"(r[3]) : "r"(addr));
}
__device__ __forceinline__ void mma16816(float* c, const uint32_t* a,
                                         uint32_t b0, uint32_t b1) {
    asm volatile(
        "mma.sync.aligned.m16n8k16.row.col.f32.bf16.bf16.f32 "
        "{%0,%1,%2,%3}, {%4,%5,%6,%7}, {%8,%9}, {%0,%1,%2,%3};"
        : "+f"(c[0]), "+f"(c[1]), "+f"(c[2]), "+f"(c[3])
        : "r"(a[0]), "r"(a[1]), "r"(a[2]), "r"(a[3]), "r"(b0), "r"(b1));
}
__device__ __forceinline__ void split_bf16(float v, __nv_bfloat16& h, __nv_bfloat16& l) {
    h = __float2bfloat16(v);
    l = __float2bfloat16(v - __bfloat162float(h));
}
__device__ __forceinline__ void cpasync16(uint32_t dst, const void* src, int sz) {
    asm volatile("cp.async.cg.shared.global [%0], [%1], 16, %2;"
                 :: "r"(dst), "l"(src), "r"(sz) : "memory");
}
#define CP_COMMIT() asm volatile("cp.async.commit_group;" ::: "memory")
#define CP_WAIT0()  asm volatile("cp.async.wait_group 0;" ::: "memory")

// ---------------- fused prep (unchanged) ----------------
#define PREP_A_N   B_
#define W1_KT      25
#define W1_NT      13
#define W2_KT      13
#define W2_NT      13
#define PREP_W1_N  (W1_KT * W1_NT)
#define PREP_W2_N  (W2_KT * W2_NT)
#define PREP_R_N   98
#define PREP_TOTAL (PREP_A_N + PREP_W1_N + PREP_W2_N + PREP_R_N)

__global__ void __launch_bounds__(256)
prep_all_kernel(const int* __restrict__ e, const int* __restrict__ q,
                const float* __restrict__ H,
                const float* __restrict__ ent_emb,
                const float* __restrict__ rel_emb,
                const float* __restrict__ W1,
                const float* __restrict__ W2) {
    const int blk = blockIdx.x;
    const int tid = threadIdx.x;

    if (blk < PREP_A_N) {
        const int b = blk;
        const float* ep = ent_emb + (long)e[b] * ED_;
        const float* hp = H + (long)b * HD_;
        const float* qp = rel_emb + (long)q[b] * RD_;
        const int i4 = tid * 4;
        if (i4 < XD_) {
            float4 v;
            if (i4 < ED_)            v = *reinterpret_cast<const float4*>(ep + i4);
            else if (i4 < ED_ + HD_) v = *reinterpret_cast<const float4*>(hp + (i4 - ED_));
            else                     v = *reinterpret_cast<const float4*>(qp + (i4 - ED_ - HD_));
            __nv_bfloat16 h0, l0, h1, l1, h2, l2, h3, l3;
            split_bf16(v.x, h0, l0); split_bf16(v.y, h1, l1);
            split_bf16(v.z, h2, l2); split_bf16(v.w, h3, l3);
            long o2 = ((long)b * XD_ + i4) >> 1;
            reinterpret_cast<__nv_bfloat162*>(g_Ah)[o2]     = __nv_bfloat162(h0, h1);
            reinterpret_cast<__nv_bfloat162*>(g_Ah)[o2 + 1] = __nv_bfloat162(h2, h3);
            reinterpret_cast<__nv_bfloat162*>(g_Al)[o2]     = __nv_bfloat162(l0, l1);
            reinterpret_cast<__nv_bfloat162*>(g_Al)[o2 + 1] = __nv_bfloat162(l2, l3);
        }
        return;
    }

    if (blk < PREP_A_N + PREP_W1_N + PREP_W2_N) {
        __shared__ float tile[32][33];
        const bool is1 = (blk < PREP_A_N + PREP_W1_N);
        const int t = is1 ? (blk - PREP_A_N) : (blk - PREP_A_N - PREP_W1_N);
        const int K = is1 ? XD_ : AD_;
        const int N = AD_;
        const int NT = is1 ? W1_NT : W2_NT;
        const float* W = is1 ? W1 : W2;
        __nv_bfloat16* WTh = is1 ? g_W1Th : g_W2Th;
        __nv_bfloat16* WTl = is1 ? g_W1Tl : g_W2Tl;
        const int kt = t / NT, nt = t % NT;
        const int k0 = kt * 32, n0 = nt * 32;
        const int tx = tid & 31, ty = tid >> 5;

        #pragma unroll
        for (int r = 0; r < 4; r++) {
            int k = k0 + ty + r * 8;
            int n = n0 + tx;
            if (k < K && n < N) tile[ty + r * 8][tx] = W[(long)k * N + n];
        }
        __syncthreads();
        #pragma unroll
        for (int r = 0; r < 4; r++) {
            int n = n0 + ty + r * 8;
            int k = k0 + tx;
            if (k < K && n < N) {
                __nv_bfloat16 h, l;
                split_bf16(tile[tx][ty + r * 8], h, l);
                WTh[(long)n * K + k] = h;
                WTl[(long)n * K + k] = l;
            }
        }
        return;
    }

    {
        const int t = blk - (PREP_A_N + PREP_W1_N + PREP_W2_N);
        const int idx = (t * 256 + tid) * 4;
        if (idx < NR_ * RD_) {
            float4 v = *reinterpret_cast<const float4*>(rel_emb + idx);
            __nv_bfloat16 h0, l0, h1, l1, h2, l2, h3, l3;
            split_bf16(v.x, h0, l0); split_bf16(v.y, h1, l1);
            split_bf16(v.z, h2, l2); split_bf16(v.w, h3, l3);
            long o2 = idx >> 1;
            reinterpret_cast<__nv_bfloat162*>(g_Rh)[o2]     = __nv_bfloat162(h0, h1);
            reinterpret_cast<__nv_bfloat162*>(g_Rh)[o2 + 1] = __nv_bfloat162(h2, h3);
            reinterpret_cast<__nv_bfloat162*>(g_Rl)[o2]     = __nv_bfloat162(l0, l1);
            reinterpret_cast<__nv_bfloat162*>(g_Rl)[o2 + 1] = __nv_bfloat162(l2, l3);
        }
        return;
    }
}

// ---------------- warp-MMA GEMM: BK=64, SW128 smem, 1 sync/iter ----------------
// smem: 4 arrays (Ah, Al, Bh, Bl) x 2 bufs x 8192 B = 65536 B -> 3 blocks/SM
#define BUFSZ 8192
#define OFF_AH 0
#define OFF_AL (2 * BUFSZ)
#define OFF_BH (4 * BUFSZ)
#define OFF_BL (6 * BUFSZ)
#define MMA_SMEM (8 * BUFSZ)    // 65536

template<int MODE>
__global__ void __launch_bounds__(256)
mma_kernel(const float* __restrict__ bias) {
    constexpr int KREAL = (MODE == 0) ? 800 : (MODE == 1) ? 400 : 200;
    constexpr int NN    = (MODE == 2) ? 500 : 400;
    constexpr int NT    = (KREAL + 63) / 64;

    extern __shared__ __align__(16) uint8_t dyn[];
    const uint32_t sb = smem_u32(dyn);

    const int tid  = threadIdx.x;
    const int wid  = tid >> 5;
    const int lane = tid & 31;
    const int bm = blockIdx.y * 64;
    const int bn = blockIdx.x * 64;

    const __nv_bfloat16* Ah = (MODE == 0) ? g_Ah : (MODE == 1) ? g_h1h : g_X2h;
    const __nv_bfloat16* Al = (MODE == 0) ? g_Al : (MODE == 1) ? g_h1l : g_X2l;
    const __nv_bfloat16* Bh = (MODE == 0) ? g_W1Th : (MODE == 1) ? g_W2Th : g_Rh;
    const __nv_bfloat16* Bl = (MODE == 0) ? g_W1Tl : (MODE == 1) ? g_W2Tl : g_Rl;

    const int lrow = tid >> 2;          // 0..63
    const int lseg0 = tid & 3;          // segs lseg0, lseg0+4
    const int nrow = bn + lrow;
    const bool nok = (nrow < NN);

    auto issue = [&](int t, int buf) {
        #pragma unroll
        for (int ss = 0; ss < 2; ss++) {
            const int seg = lseg0 + ss * 4;
            const int kg = t * 64 + seg * 8;
            const bool kok = (kg < KREAL);
            const int kcl = kok ? kg : 0;
            const uint32_t so = (uint32_t)buf * BUFSZ + SW128((uint32_t)(lrow * 128 + seg * 16));
            const long aoff = (long)(bm + lrow) * KREAL + kcl;
            const long boff = (long)(nok ? nrow : 0) * KREAL + kcl;
            const int szA = kok ? 16 : 0;
            const int szB = (kok && nok) ? 16 : 0;
            cpasync16(sb + OFF_AH + so, Ah + aoff, szA);
            cpasync16(sb + OFF_AL + so, Al + aoff, szA);
            cpasync16(sb + OFF_BH + so, Bh + boff, szB);
            cpasync16(sb + OFF_BL + so, Bl + boff, szB);
        }
    };

    const int m0w = (wid >> 1) * 16;
    const int n0w = (wid & 1) * 32;
    const int arow = m0w + (lane & 15);
    const int acolb = (lane >> 4) * 16;

    float c[4][4] = {};

    issue(0, 0);
    CP_COMMIT();

    for (int t = 0; t < NT; t++) {
        const int cur = t & 1;
        CP_WAIT0();            // tile t landed
        __syncthreads();       // publish tile t; all warps done with buffer cur^1
        if (t + 1 < NT) { issue(t + 1, cur ^ 1); CP_COMMIT(); }

        const uint32_t bAh = sb + OFF_AH + cur * BUFSZ;
        const uint32_t bAl = sb + OFF_AL + cur * BUFSZ;
        const uint32_t bBh = sb + OFF_BH + cur * BUFSZ;
        const uint32_t bBl = sb + OFF_BL + cur * BUFSZ;

        #pragma unroll
        for (int kc = 0; kc < 4; kc++) {
            const uint32_t kb = kc * 32 + acolb;
            uint32_t ah[4], al[4];
            ldsm4(ah, bAh + SW128((uint32_t)(arow * 128) + kb));
            ldsm4(al, bAl + SW128((uint32_t)(arow * 128) + kb));

            #pragma unroll
            for (int np = 0; np < 2; np++) {
                const int brow = n0w + np * 16 + (lane & 15);
                uint32_t bh[4], bl[4];
                ldsm4(bh, bBh + SW128((uint32_t)(brow * 128) + kb));
                ldsm4(bl, bBl + SW128((uint32_t)(brow * 128) + kb));

                float* c0 = c[np * 2 + 0];
                float* c1 = c[np * 2 + 1];
                mma16816(c0, ah, bh[0], bh[2]);
                mma16816(c0, ah, bl[0], bl[2]);
                mma16816(c0, al, bh[0], bh[2]);
                mma16816(c1, ah, bh[1], bh[3]);
                mma16816(c1, ah, bl[1], bl[3]);
                mma16816(c1, al, bh[1], bh[3]);
            }
        }
    }

    // ---------- epilogue (registers only; no smem hazard) ----------
    const int m0 = bm + m0w;
    const int n0 = bn + n0w;
    const int r0 = m0 + (lane >> 2);
    const int r1 = r0 + 8;

    #pragma unroll
    for (int q4 = 0; q4 < 4; q4++) {
        int nc = n0 + q4 * 8 + (lane & 3) * 2;
        if (nc >= NN) continue;
        float v00 = c[q4][0], v01 = c[q4][1];
        float v10 = c[q4][2], v11 = c[q4][3];
        if (MODE != 2) {
            float bb0 = bias[nc], bb1 = bias[nc + 1];
            v00 += bb0; v01 += bb1; v10 += bb0; v11 += bb1;
        }
        if (MODE == 0) {
            v00 = fmaxf(v00, 0.f); v01 = fmaxf(v01, 0.f);
            v10 = fmaxf(v10, 0.f); v11 = fmaxf(v11, 0.f);
            __nv_bfloat16 h0, l0, h1, l1;
            split_bf16(v00, h0, l0); split_bf16(v01, h1, l1);
            *reinterpret_cast<__nv_bfloat162*>(&g_h1h[(long)r0 * AD_ + nc]) = __nv_bfloat162(h0, h1);
            *reinterpret_cast<__nv_bfloat162*>(&g_h1l[(long)r0 * AD_ + nc]) = __nv_bfloat162(l0, l1);
            split_bf16(v10, h0, l0); split_bf16(v11, h1, l1);
            *reinterpret_cast<__nv_bfloat162*>(&g_h1h[(long)r1 * AD_ + nc]) = __nv_bfloat162(h0, h1);
            *reinterpret_cast<__nv_bfloat162*>(&g_h1l[(long)r1 * AD_ + nc]) = __nv_bfloat162(l0, l1);
        } else if (MODE == 1) {
            *reinterpret_cast<float2*>(&g_X2[(long)r0 * AD_ + nc]) = make_float2(v00, v01);
            *reinterpret_cast<float2*>(&g_X2[(long)r1 * AD_ + nc]) = make_float2(v10, v11);
            if (nc < 200) {
                __nv_bfloat16 h0, l0, h1, l1;
                split_bf16(v00, h0, l0); split_bf16(v01, h1, l1);
                *reinterpret_cast<__nv_bfloat162*>(&g_X2h[(long)r0 * 200 + nc]) = __nv_bfloat162(h0, h1);
                *reinterpret_cast<__nv_bfloat162*>(&g_X2l[(long)r0 * 200 + nc]) = __nv_bfloat162(l0, l1);
                split_bf16(v10, h0, l0); split_bf16(v11, h1, l1);
                *reinterpret_cast<__nv_bfloat162*>(&g_X2h[(long)r1 * 200 + nc]) = __nv_bfloat162(h0, h1);
                *reinterpret_cast<__nv_bfloat162*>(&g_X2l[(long)r1 * 200 + nc]) = __nv_bfloat162(l0, l1);
            }
        } else {
            *reinterpret_cast<float2*>(&g_P[(long)r0 * NR_ + nc]) = make_float2(v00, v01);
            *reinterpret_cast<float2*>(&g_P[(long)r1 * NR_ + nc]) = make_float2(v10, v11);
        }
    }
}

// ---------------- score (unchanged) ----------------
__device__ __forceinline__ float dot4(float4 a, float4 b) {
    return a.x * b.x + a.y * b.y + a.z * b.z + a.w * b.w;
}
__global__ void __launch_bounds__(256, 8)
score_kernel(const int* __restrict__ r_space,
             const int* __restrict__ e_space,
             const int* __restrict__ action_mask,
             const float* __restrict__ ent_emb,
             float* __restrict__ out_dist,
             float* __restrict__ out_ent) {
    const int b = blockIdx.x;
    const int tid = threadIdx.x;
    const int lane = tid & 31;
    const int warp = tid >> 5;
    const int grp = lane >> 3;
    const int gl = lane & 7;
    const unsigned FULL = 0xffffffffu;

    __shared__ float4 x2e[50];
    __shared__ float sc[A_];
    __shared__ float red[8];
    __shared__ unsigned char alist[8][32];

    if (tid < 50)
        x2e[tid] = reinterpret_cast<const float4*>(g_X2 + (long)b * AD_ + 200)[tid];
    sc[tid] = -1e30f;
    __syncthreads();

    const long base = (long)b * A_;
    const int aidx = warp * 32 + lane;
    const int my_r = r_space[base + aidx];
    const int my_e = e_space[base + aidx];
    const int my_m = action_mask[base + aidx];

    unsigned mbits = __ballot_sync(FULL, my_m != 0);
    const int cnt = __popc(mbits);
    if (my_m) alist[warp][__popc(mbits & ((1u << lane) - 1u))] = (unsigned char)lane;
    __syncwarp();

    const float* Prow = g_P + (long)b * NR_;

    for (int i0 = 0; i0 < cnt; i0 += 4) {
        int i = i0 + grp;
        bool act = (i < cnt);
        int sl = act ? (int)alist[warp][i] : 0;
        int rr = __shfl_sync(FULL, my_r, sl);
        int ee = __shfl_sync(FULL, my_e, sl);

        const float4* ep = reinterpret_cast<const float4*>(ent_emb + (long)ee * ED_);
        float s = 0.f;
        #pragma unroll
        for (int cc = 0; cc < 6; cc++) {
            float4 ev = ep[cc * 8 + gl];
            s += dot4(ev, x2e[cc * 8 + gl]);
        }
        if (gl < 2) {
            float4 ev = ep[48 + gl];
            s += dot4(ev, x2e[48 + gl]);
        }
        s += __shfl_xor_sync(FULL, s, 1);
        s += __shfl_xor_sync(FULL, s, 2);
        s += __shfl_xor_sync(FULL, s, 4);
        if (act && gl == 0) sc[warp * 32 + sl] = s + Prow[rr];
    }
    __syncthreads();

    float v = sc[tid];
    float mx = v;
    #pragma unroll
    for (int o = 16; o; o >>= 1) mx = fmaxf(mx, __shfl_xor_sync(FULL, mx, o));
    if (lane == 0) red[warp] = mx;
    __syncthreads();
    if (warp == 0) {
        float mm = red[lane & 7];
        #pragma unroll
        for (int o = 4; o; o >>= 1) mm = fmaxf(mm, __shfl_xor_sync(FULL, mm, o));
        if (lane == 0) red[0] = mm;
    }
    __syncthreads();
    mx = red[0];
    __syncthreads();

    float ev = expf(v - mx);
    float sm = ev;
    #pragma unroll
    for (int o = 16; o; o >>= 1) sm += __shfl_xor_sync(FULL, sm, o);
    if (lane == 0) red[warp] = sm;
    __syncthreads();
    if (warp == 0) {
        float ss = red[lane & 7];
        #pragma unroll
        for (int o = 4; o; o >>= 1) ss += __shfl_xor_sync(FULL, ss, o);
        if (lane == 0) red[0] = ss;
    }
    __syncthreads();
    float total = red[0];
    __syncthreads();

    float p = ev / total;
    out_dist[base + tid] = p;

    float t = p * logf(fmaxf(p, 1e-20f));
    float es = t;
    #pragma unroll
    for (int o = 16; o; o >>= 1) es += __shfl_xor_sync(FULL, es, o);
    if (lane == 0) red[warp] = es;
    __syncthreads();
    if (warp == 0) {
        float ss = red[lane & 7];
        #pragma unroll
        for (int o = 4; o; o >>= 1) ss += __shfl_xor_sync(FULL, ss, o);
        if (lane == 0) out_ent[b] = -ss;
    }
}

// ---------------- launch ----------------
extern "C" void kernel_launch(void* const* d_in, const int* in_sizes, int n_in,
                              void* d_out, int out_size) {
    const int*   e        = (const int*)  d_in[0];
    const int*   q        = (const int*)  d_in[1];
    const int*   r_space  = (const int*)  d_in[2];
    const int*   e_space  = (const int*)  d_in[3];
    const int*   mask     = (const int*)  d_in[4];
    const float* H        = (const float*)d_in[5];
    const float* ent_emb  = (const float*)d_in[6];
    const float* rel_emb  = (const float*)d_in[7];
    const float* W1       = (const float*)d_in[8];
    const float* b1       = (const float*)d_in[9];
    const float* W2       = (const float*)d_in[10];
    const float* b2       = (const float*)d_in[11];

    float* out_dist = (float*)d_out;
    float* out_ent  = (float*)d_out + (long)B_ * A_;

    cudaFuncSetAttribute(mma_kernel<0>, cudaFuncAttributeMaxDynamicSharedMemorySize, MMA_SMEM);
    cudaFuncSetAttribute(mma_kernel<1>, cudaFuncAttributeMaxDynamicSharedMemorySize, MMA_SMEM);
    cudaFuncSetAttribute(mma_kernel<2>, cudaFuncAttributeMaxDynamicSharedMemorySize, MMA_SMEM);

    prep_all_kernel<<<PREP_TOTAL, 256>>>(e, q, H, ent_emb, rel_emb, W1, W2);

    mma_kernel<0><<<dim3(7, 32), 256, MMA_SMEM>>>(b1);
    mma_kernel<1><<<dim3(7, 32), 256, MMA_SMEM>>>(b2);
    mma_kernel<2><<<dim3(8, 32), 256, MMA_SMEM>>>(nullptr);

    score_kernel<<<B_, 256>>>(r_space, e_space, mask, ent_emb,
                              out_dist, out_ent);
}